// round 6
// baseline (speedup 1.0000x reference)
#include <cuda_runtime.h>
#include <cuda_bf16.h>

#define N_NODES 50000
#define N_EDGES 1600000
#define C_OUT   256
#define SCAN_BLOCKS 196   // ceil(50000/256)
#define W_TOTAL (256*128 + 256*256 + 256*256)   // all weights, hi/lo split once

// ---------------- scratch (static device globals; allocation-free) ----------
__device__ int   g_is64;
__device__ int   g_src[N_EDGES];
__device__ int   g_dst[N_EDGES];
__device__ float g_ew[N_EDGES];
__device__ int   g_srcS[N_EDGES];
__device__ float g_ewS[N_EDGES];
__device__ int   g_deg[N_NODES];
__device__ int   g_blkoff[SCAN_BLOCKS];
__device__ int   g_rowoff[N_NODES + 1];
__device__ int   g_cursor[N_NODES];
__device__ float g_aggH[(size_t)N_NODES * C_OUT];   // tf32-hi of aggregate
__device__ float g_aggL[(size_t)N_NODES * C_OUT];   // tf32 residual (lo)
__device__ float g_h[(size_t)N_NODES * C_OUT];
__device__ float g_WH[W_TOTAL];
__device__ float g_WL[W_TOTAL];

// ---------------- tf32 helpers ----------------------------------------------
__device__ __forceinline__ unsigned f2tf32(float x) {
    unsigned r;
    asm("cvt.rna.tf32.f32 %0, %1;" : "=r"(r) : "f"(x));
    return r;
}

// d += A(16x8 tf32) * B(8x8 tf32), fp32 accumulate
__device__ __forceinline__ void mma_tf32(float c[4], const unsigned a[4],
                                         const unsigned b[2]) {
    asm("mma.sync.aligned.m16n8k8.row.col.f32.tf32.tf32.f32 "
        "{%0,%1,%2,%3}, {%4,%5,%6,%7}, {%8,%9}, {%0,%1,%2,%3};"
        : "+f"(c[0]), "+f"(c[1]), "+f"(c[2]), "+f"(c[3])
        : "r"(a[0]), "r"(a[1]), "r"(a[2]), "r"(a[3]), "r"(b[0]), "r"(b[1]));
}

// ---------------- int64-vs-int32 edge_index detection -----------------------
__global__ void detect_kernel(const int* __restrict__ ei_words) {
    __shared__ int nz;
    if (threadIdx.x == 0) nz = 0;
    __syncthreads();
    if (ei_words[2 * threadIdx.x + 1] != 0) atomicOr(&nz, 1);
    __syncthreads();
    if (threadIdx.x == 0) g_is64 = (nz == 0) ? 1 : 0;
}

// split a weight blob into tf32 hi / residual lo (once per launch)
__global__ void split_w_kernel(const float* __restrict__ src, int n, int off) {
    int i = blockIdx.x * blockDim.x + threadIdx.x;
    if (i >= n) return;
    float v = src[i];
    float hi = __uint_as_float(f2tf32(v));
    g_WH[off + i] = hi;
    g_WL[off + i] = __uint_as_float(f2tf32(v - hi));
}

// decode edge_index, compute ew = mean(edge_attr, -1), histogram dst degrees
__global__ void build_edges_kernel(const int* __restrict__ ei,
                                   const float* __restrict__ ea) {
    int e = blockIdx.x * blockDim.x + threadIdx.x;
    if (e >= N_EDGES) return;
    int s, d;
    if (g_is64) {
        s = ei[2 * (size_t)e];
        d = ei[2 * (size_t)N_EDGES + 2 * (size_t)e];
    } else {
        s = ei[e];
        d = ei[N_EDGES + e];
    }
    g_src[e] = s;
    g_dst[e] = d;
    const float4* a4 = (const float4*)(ea + (size_t)e * 8);
    float4 u = a4[0];
    float4 v = a4[1];
    g_ew[e] = (u.x + u.y + u.z + u.w + v.x + v.y + v.z + v.w) * 0.125f;
    atomicAdd(&g_deg[d], 1);
}

// ---------------- decoupled 3-phase exclusive scan ---------------------------
__global__ void scan_p1_kernel() {
    int i = blockIdx.x * 256 + threadIdx.x;
    int v = (i < N_NODES) ? g_deg[i] : 0;
#pragma unroll
    for (int o = 16; o > 0; o >>= 1) v += __shfl_down_sync(~0u, v, o);
    __shared__ int ws[8];
    int lane = threadIdx.x & 31, wid = threadIdx.x >> 5;
    if (lane == 0) ws[wid] = v;
    __syncthreads();
    if (threadIdx.x == 0) {
        int s = 0;
#pragma unroll
        for (int w = 0; w < 8; w++) s += ws[w];
        g_blkoff[blockIdx.x] = s;
    }
}

__global__ void scan_p2_kernel() {
    int tid = threadIdx.x;  // 256 threads
    int v = (tid < SCAN_BLOCKS) ? g_blkoff[tid] : 0;
    int lane = tid & 31, wid = tid >> 5;
    int x = v;
#pragma unroll
    for (int o = 1; o < 32; o <<= 1) {
        int t = __shfl_up_sync(~0u, x, o);
        if (lane >= o) x += t;
    }
    __shared__ int ws[8];
    if (lane == 31) ws[wid] = x;
    __syncthreads();
    if (wid == 0 && lane < 8) {
        int w = ws[lane];
#pragma unroll
        for (int o = 1; o < 8; o <<= 1) {
            int t = __shfl_up_sync(0xffu, w, o);
            if (lane >= o) w += t;
        }
        ws[lane] = w;
    }
    __syncthreads();
    int excl = (x - v) + (wid > 0 ? ws[wid - 1] : 0);
    if (tid < SCAN_BLOCKS) g_blkoff[tid] = excl;
    if (tid == 0) g_rowoff[N_NODES] = N_EDGES;
}

__global__ void scan_p3_kernel() {
    int i = blockIdx.x * 256 + threadIdx.x;
    int v = (i < N_NODES) ? g_deg[i] : 0;
    int lane = threadIdx.x & 31, wid = threadIdx.x >> 5;
    int x = v;
#pragma unroll
    for (int o = 1; o < 32; o <<= 1) {
        int t = __shfl_up_sync(~0u, x, o);
        if (lane >= o) x += t;
    }
    __shared__ int ws[8];
    if (lane == 31) ws[wid] = x;
    __syncthreads();
    if (wid == 0 && lane < 8) {
        int w = ws[lane];
#pragma unroll
        for (int o = 1; o < 8; o <<= 1) {
            int t = __shfl_up_sync(0xffu, w, o);
            if (lane >= o) w += t;
        }
        ws[lane] = w;
    }
    __syncthreads();
    int excl = (x - v) + (wid > 0 ? ws[wid - 1] : 0) + g_blkoff[blockIdx.x];
    if (i < N_NODES) {
        g_rowoff[i] = excl;
        g_cursor[i] = excl;
    }
}

// scatter edges into CSR buckets (sorted by dst)
__global__ void fill_kernel() {
    int e = blockIdx.x * blockDim.x + threadIdx.x;
    if (e >= N_EDGES) return;
    int d = g_dst[e];
    int p = atomicAdd(&g_cursor[d], 1);
    g_srcS[p] = g_src[e];
    g_ewS[p] = g_ew[e];
}

// ---------------- gather-aggregate + tf32 split epilogue --------------------
// out_i = sum_{e: dst=i} in[src_e] * w_e ; writes hi/lo tf32 split of result.
template <int C, bool USE_W>
__global__ void gather_kernel(const float* __restrict__ in,
                              float* __restrict__ outH,
                              float* __restrict__ outL) {
    constexpr int L = C / 4;        // lanes per node
    constexpr int G = 256 / L;      // nodes per 256-thread block
    int grp  = threadIdx.x / L;
    int lane = threadIdx.x % L;
    int node = blockIdx.x * G + grp;
    if (node >= N_NODES) return;

    int e0 = g_rowoff[node];
    int e1 = g_rowoff[node + 1];
    const float4* in4 = (const float4*)in;
    float4 acc = make_float4(0.f, 0.f, 0.f, 0.f);

    int e = e0;
    for (; e + 4 <= e1; e += 4) {
        int s0 = g_srcS[e], s1 = g_srcS[e + 1];
        int s2 = g_srcS[e + 2], s3 = g_srcS[e + 3];
        float w0 = USE_W ? g_ewS[e] : 1.0f;
        float w1 = USE_W ? g_ewS[e + 1] : 1.0f;
        float w2 = USE_W ? g_ewS[e + 2] : 1.0f;
        float w3 = USE_W ? g_ewS[e + 3] : 1.0f;
        float4 v0 = in4[(size_t)s0 * L + lane];
        float4 v1 = in4[(size_t)s1 * L + lane];
        float4 v2 = in4[(size_t)s2 * L + lane];
        float4 v3 = in4[(size_t)s3 * L + lane];
        acc.x = fmaf(v0.x, w0, acc.x); acc.y = fmaf(v0.y, w0, acc.y);
        acc.z = fmaf(v0.z, w0, acc.z); acc.w = fmaf(v0.w, w0, acc.w);
        acc.x = fmaf(v1.x, w1, acc.x); acc.y = fmaf(v1.y, w1, acc.y);
        acc.z = fmaf(v1.z, w1, acc.z); acc.w = fmaf(v1.w, w1, acc.w);
        acc.x = fmaf(v2.x, w2, acc.x); acc.y = fmaf(v2.y, w2, acc.y);
        acc.z = fmaf(v2.z, w2, acc.z); acc.w = fmaf(v2.w, w2, acc.w);
        acc.x = fmaf(v3.x, w3, acc.x); acc.y = fmaf(v3.y, w3, acc.y);
        acc.z = fmaf(v3.z, w3, acc.z); acc.w = fmaf(v3.w, w3, acc.w);
    }
    for (; e < e1; e++) {
        int sa = g_srcS[e];
        float wa = USE_W ? g_ewS[e] : 1.0f;
        float4 va = in4[(size_t)sa * L + lane];
        acc.x = fmaf(va.x, wa, acc.x); acc.y = fmaf(va.y, wa, acc.y);
        acc.z = fmaf(va.z, wa, acc.z); acc.w = fmaf(va.w, wa, acc.w);
    }
    float hx = __uint_as_float(f2tf32(acc.x));
    float hy = __uint_as_float(f2tf32(acc.y));
    float hz = __uint_as_float(f2tf32(acc.z));
    float hw = __uint_as_float(f2tf32(acc.w));
    ((float4*)outH)[(size_t)node * L + lane] = make_float4(hx, hy, hz, hw);
    ((float4*)outL)[(size_t)node * L + lane] = make_float4(
        __uint_as_float(f2tf32(acc.x - hx)),
        __uint_as_float(f2tf32(acc.y - hy)),
        __uint_as_float(f2tf32(acc.z - hz)),
        __uint_as_float(f2tf32(acc.w - hw)));
}

// ---------------- tensor-core GEMM (3xTF32, pre-split operands) -------------
// out = A @ W^T + epilogue.  BM=128, BN=128, BK=16, 512 threads = 16 warps
// (4m x 4n), warp tile 32x32 = 2 m-atoms x 4 n-atoms.
// Operands arrive pre-split (Ah/Al from gather, Bh/Bl from split_w) so the
// mainloop is: 4x LDG.128 + 4x STS.128 per thread + frag LDS + 24 HMMA.
template <int K, bool BN_RELU>
__global__ void gemm_tc_kernel(const float* __restrict__ Ah,
                               const float* __restrict__ Al,
                               const float* __restrict__ Bh,
                               const float* __restrict__ Bl,
                               const float* __restrict__ bias,
                               const float* __restrict__ gam,
                               const float* __restrict__ bet,
                               const float* __restrict__ mu,
                               const float* __restrict__ var,
                               float* __restrict__ out) {
    constexpr int BM = 128, BN = 128, BK = 16;
    constexpr int PK = 20;  // row pitch in words: frag LDS conflict-free
    __shared__ __align__(16) float sAh[BM][PK];
    __shared__ __align__(16) float sAl[BM][PK];
    __shared__ __align__(16) float sBh[BN][PK];
    __shared__ __align__(16) float sBl[BN][PK];

    int m0 = blockIdx.x * BM;
    int n0 = blockIdx.y * BN;
    int tid = threadIdx.x;
    int lane = tid & 31;
    int g = lane >> 2;        // 0..7
    int t = lane & 3;         // 0..3
    int wid = tid >> 5;       // 0..15
    int wm = wid & 3;         // warp m index (0..3)
    int wn = wid >> 2;        // warp n index (0..3)

    // loader mapping: 512 threads, one float4 per tile each
    int lrow = tid >> 2;            // 0..127
    int lkq  = (tid & 3) * 4;       // 0,4,8,12

    float acc[2][4][4];
#pragma unroll
    for (int i = 0; i < 2; i++)
#pragma unroll
        for (int j = 0; j < 4; j++)
#pragma unroll
            for (int c = 0; c < 4; c++) acc[i][j][c] = 0.f;

    for (int kt = 0; kt < K; kt += BK) {
        {
            int row = m0 + lrow;
            float4 ah = make_float4(0.f, 0.f, 0.f, 0.f), al = ah;
            if (row < N_NODES) {
                ah = *(const float4*)(Ah + (size_t)row * K + kt + lkq);
                al = *(const float4*)(Al + (size_t)row * K + kt + lkq);
            }
            *(float4*)&sAh[lrow][lkq] = ah;
            *(float4*)&sAl[lrow][lkq] = al;
            const float* bhp = Bh + (size_t)(n0 + lrow) * K + kt + lkq;
            const float* blp = Bl + (size_t)(n0 + lrow) * K + kt + lkq;
            *(float4*)&sBh[lrow][lkq] = *(const float4*)bhp;
            *(float4*)&sBl[lrow][lkq] = *(const float4*)blp;
        }
        __syncthreads();

#pragma unroll
        for (int ko = 0; ko < BK; ko += 8) {
            unsigned ah[2][4], al[2][4], bh[4][2], bl[4][2];
#pragma unroll
            for (int i = 0; i < 2; i++) {
                int rm = wm * 32 + i * 16;
                ah[i][0] = __float_as_uint(sAh[rm + g][ko + t]);
                ah[i][1] = __float_as_uint(sAh[rm + g + 8][ko + t]);
                ah[i][2] = __float_as_uint(sAh[rm + g][ko + t + 4]);
                ah[i][3] = __float_as_uint(sAh[rm + g + 8][ko + t + 4]);
                al[i][0] = __float_as_uint(sAl[rm + g][ko + t]);
                al[i][1] = __float_as_uint(sAl[rm + g + 8][ko + t]);
                al[i][2] = __float_as_uint(sAl[rm + g][ko + t + 4]);
                al[i][3] = __float_as_uint(sAl[rm + g + 8][ko + t + 4]);
            }
#pragma unroll
            for (int j = 0; j < 4; j++) {
                int cn = wn * 32 + j * 8;
                bh[j][0] = __float_as_uint(sBh[cn + g][ko + t]);
                bh[j][1] = __float_as_uint(sBh[cn + g][ko + t + 4]);
                bl[j][0] = __float_as_uint(sBl[cn + g][ko + t]);
                bl[j][1] = __float_as_uint(sBl[cn + g][ko + t + 4]);
            }
#pragma unroll
            for (int i = 0; i < 2; i++)
#pragma unroll
                for (int j = 0; j < 4; j++) {
                    mma_tf32(acc[i][j], ah[i], bh[j]);
                    mma_tf32(acc[i][j], al[i], bh[j]);
                    mma_tf32(acc[i][j], ah[i], bl[j]);
                }
        }
        __syncthreads();
    }

    // ---- epilogue: +bias, optional BN(eval)+ReLU, float2 stores ----
#pragma unroll
    for (int j = 0; j < 4; j++) {
        int n = n0 + wn * 32 + j * 8 + 2 * t;
        float b0 = bias[n], b1 = bias[n + 1];
        float s0 = 0.f, s1 = 0.f, t0 = 0.f, t1 = 0.f;
        if (BN_RELU) {
            s0 = gam[n] * rsqrtf(var[n] + 1e-5f);
            t0 = bet[n] - mu[n] * s0;
            s1 = gam[n + 1] * rsqrtf(var[n + 1] + 1e-5f);
            t1 = bet[n + 1] - mu[n + 1] * s1;
        }
#pragma unroll
        for (int i = 0; i < 2; i++) {
            int r0 = m0 + wm * 32 + i * 16 + g;
            int r1 = r0 + 8;
            float z0 = acc[i][j][0] + b0;
            float z1 = acc[i][j][1] + b1;
            float z2 = acc[i][j][2] + b0;
            float z3 = acc[i][j][3] + b1;
            if (BN_RELU) {
                z0 = fmaxf(fmaf(z0, s0, t0), 0.f);
                z1 = fmaxf(fmaf(z1, s1, t1), 0.f);
                z2 = fmaxf(fmaf(z2, s0, t0), 0.f);
                z3 = fmaxf(fmaf(z3, s1, t1), 0.f);
            }
            if (r0 < N_NODES)
                *(float2*)(out + (size_t)r0 * C_OUT + n) = make_float2(z0, z1);
            if (r1 < N_NODES)
                *(float2*)(out + (size_t)r1 * C_OUT + n) = make_float2(z2, z3);
        }
    }
}

// ---------------- launch ----------------------------------------------------
extern "C" void kernel_launch(void* const* d_in, const int* in_sizes, int n_in,
                              void* d_out, int out_size) {
    const float* x   = (const float*)d_in[0];
    const int*   ei  = (const int*)d_in[1];
    const float* ea  = (const float*)d_in[2];
    const float* W1  = (const float*)d_in[3];
    const float* b1  = (const float*)d_in[4];
    const float* g1  = (const float*)d_in[5];
    const float* be1 = (const float*)d_in[6];
    const float* m1  = (const float*)d_in[7];
    const float* v1  = (const float*)d_in[8];
    const float* W2  = (const float*)d_in[9];
    const float* b2  = (const float*)d_in[10];
    const float* g2  = (const float*)d_in[11];
    const float* be2 = (const float*)d_in[12];
    const float* m2  = (const float*)d_in[13];
    const float* v2  = (const float*)d_in[14];
    const float* W3  = (const float*)d_in[15];
    const float* b3  = (const float*)d_in[16];
    float* out = (float*)d_out;

    void *p_aggH, *p_aggL, *p_h, *p_deg, *p_WH, *p_WL;
    cudaGetSymbolAddress(&p_aggH, g_aggH);
    cudaGetSymbolAddress(&p_aggL, g_aggL);
    cudaGetSymbolAddress(&p_h, g_h);
    cudaGetSymbolAddress(&p_deg, g_deg);
    cudaGetSymbolAddress(&p_WH, g_WH);
    cudaGetSymbolAddress(&p_WL, g_WL);
    float* aggH = (float*)p_aggH;
    float* aggL = (float*)p_aggL;
    float* h    = (float*)p_h;
    float* WH   = (float*)p_WH;
    float* WL   = (float*)p_WL;
    const int offW2 = 256 * 128;
    const int offW3 = offW2 + 256 * 256;

    // ---- CSR build + weight split (once) ----
    detect_kernel<<<1, 64>>>(ei);
    cudaMemsetAsync(p_deg, 0, N_NODES * sizeof(int));
    build_edges_kernel<<<(N_EDGES + 255) / 256, 256>>>(ei, ea);
    split_w_kernel<<<(256 * 128 + 255) / 256, 256>>>(W1, 256 * 128, 0);
    split_w_kernel<<<(256 * 256 + 255) / 256, 256>>>(W2, 256 * 256, offW2);
    split_w_kernel<<<(256 * 256 + 255) / 256, 256>>>(W3, 256 * 256, offW3);
    scan_p1_kernel<<<SCAN_BLOCKS, 256>>>();
    scan_p2_kernel<<<1, 256>>>();
    scan_p3_kernel<<<SCAN_BLOCKS, 256>>>();
    fill_kernel<<<(N_EDGES + 255) / 256, 256>>>();

    dim3 ggrid((N_NODES + 127) / 128, 2);  // 391 x 2, BM=BN=128

    // ---- layer 1: aggregate x (C=128), GEMM K=128 + BN1 + ReLU ----
    gather_kernel<128, true><<<(N_NODES + 7) / 8, 256>>>(x, aggH, aggL);
    gemm_tc_kernel<128, true><<<ggrid, 512>>>(aggH, aggL, WH, WL,
                                              b1, g1, be1, m1, v1, h);

    // ---- layer 2: aggregate h (C=256), GEMM K=256 + BN2 + ReLU ----
    gather_kernel<256, true><<<(N_NODES + 3) / 4, 256>>>(h, aggH, aggL);
    gemm_tc_kernel<256, true><<<ggrid, 512>>>(aggH, aggL, WH + offW2, WL + offW2,
                                              b2, g2, be2, m2, v2, h);

    // ---- layer 3: aggregate h (C=256, no edge weight), GEMM K=256 + bias ----
    gather_kernel<256, false><<<(N_NODES + 3) / 4, 256>>>(h, aggH, aggL);
    gemm_tc_kernel<256, false><<<ggrid, 512>>>(aggH, aggL, WH + offW3, WL + offW3,
                                               b3, nullptr, nullptr, nullptr,
                                               nullptr, out);
}

// round 8
// speedup vs baseline: 1.4824x; 1.4824x over previous
#include <cuda_runtime.h>
#include <cuda_fp16.h>

#define N_NODES 50000
#define N_EDGES 1600000
#define C_OUT   256
#define SCAN_BLOCKS 196   // ceil(50000/256)
#define W_TOTAL (256*128 + 256*256 + 256*256)

// ---------------- scratch (static device globals; allocation-free) ----------
__device__ int    g_is64;
__device__ int    g_src[N_EDGES];
__device__ int    g_dst[N_EDGES];
__device__ float  g_ew[N_EDGES];
__device__ int    g_srcS[N_EDGES];
__device__ float  g_ewS[N_EDGES];
__device__ int    g_deg[N_NODES];
__device__ int    g_blkoff[SCAN_BLOCKS];
__device__ int    g_rowoff[N_NODES + 1];
__device__ int    g_cursor[N_NODES];
__device__ __half g_aggH[(size_t)N_NODES * C_OUT];   // fp16 hi of aggregate
__device__ __half g_aggL[(size_t)N_NODES * C_OUT];   // fp16 residual
__device__ float  g_h[(size_t)N_NODES * C_OUT];
__device__ __half g_WH[W_TOTAL];
__device__ __half g_WL[W_TOTAL];

__device__ __forceinline__ unsigned h2_as_u32(half2 v) {
    unsigned u;
    memcpy(&u, &v, 4);
    return u;
}

// d(16x8 f32) += A(16x16 f16) * B(16x8 f16)
__device__ __forceinline__ void mma_f16(float c[4], const unsigned a[4],
                                        const unsigned b[2]) {
    asm("mma.sync.aligned.m16n8k16.row.col.f32.f16.f16.f32 "
        "{%0,%1,%2,%3}, {%4,%5,%6,%7}, {%8,%9}, {%0,%1,%2,%3};"
        : "+f"(c[0]), "+f"(c[1]), "+f"(c[2]), "+f"(c[3])
        : "r"(a[0]), "r"(a[1]), "r"(a[2]), "r"(a[3]), "r"(b[0]), "r"(b[1]));
}

// ---------------- int64-vs-int32 edge_index detection -----------------------
__global__ void detect_kernel(const int* __restrict__ ei_words) {
    __shared__ int nz;
    if (threadIdx.x == 0) nz = 0;
    __syncthreads();
    if (ei_words[2 * threadIdx.x + 1] != 0) atomicOr(&nz, 1);
    __syncthreads();
    if (threadIdx.x == 0) g_is64 = (nz == 0) ? 1 : 0;
}

// split a weight blob into fp16 hi / fp16 residual (once per launch)
__global__ void split_w_kernel(const float* __restrict__ src, int n, int off) {
    int i = blockIdx.x * blockDim.x + threadIdx.x;
    if (i >= n) return;
    float v = src[i];
    __half h = __float2half_rn(v);
    g_WH[off + i] = h;
    g_WL[off + i] = __float2half_rn(v - __half2float(h));
}

// decode edge_index, compute ew = mean(edge_attr, -1), histogram dst degrees
__global__ void build_edges_kernel(const int* __restrict__ ei,
                                   const float* __restrict__ ea) {
    int e = blockIdx.x * blockDim.x + threadIdx.x;
    if (e >= N_EDGES) return;
    int s, d;
    if (g_is64) {
        s = ei[2 * (size_t)e];
        d = ei[2 * (size_t)N_EDGES + 2 * (size_t)e];
    } else {
        s = ei[e];
        d = ei[N_EDGES + e];
    }
    g_src[e] = s;
    g_dst[e] = d;
    const float4* a4 = (const float4*)(ea + (size_t)e * 8);
    float4 u = a4[0];
    float4 v = a4[1];
    g_ew[e] = (u.x + u.y + u.z + u.w + v.x + v.y + v.z + v.w) * 0.125f;
    atomicAdd(&g_deg[d], 1);
}

// ---------------- decoupled 3-phase exclusive scan ---------------------------
__global__ void scan_p1_kernel() {
    int i = blockIdx.x * 256 + threadIdx.x;
    int v = (i < N_NODES) ? g_deg[i] : 0;
#pragma unroll
    for (int o = 16; o > 0; o >>= 1) v += __shfl_down_sync(~0u, v, o);
    __shared__ int ws[8];
    int lane = threadIdx.x & 31, wid = threadIdx.x >> 5;
    if (lane == 0) ws[wid] = v;
    __syncthreads();
    if (threadIdx.x == 0) {
        int s = 0;
#pragma unroll
        for (int w = 0; w < 8; w++) s += ws[w];
        g_blkoff[blockIdx.x] = s;
    }
}

__global__ void scan_p2_kernel() {
    int tid = threadIdx.x;  // 256 threads
    int v = (tid < SCAN_BLOCKS) ? g_blkoff[tid] : 0;
    int lane = tid & 31, wid = tid >> 5;
    int x = v;
#pragma unroll
    for (int o = 1; o < 32; o <<= 1) {
        int t = __shfl_up_sync(~0u, x, o);
        if (lane >= o) x += t;
    }
    __shared__ int ws[8];
    if (lane == 31) ws[wid] = x;
    __syncthreads();
    if (wid == 0 && lane < 8) {
        int w = ws[lane];
#pragma unroll
        for (int o = 1; o < 8; o <<= 1) {
            int t = __shfl_up_sync(0xffu, w, o);
            if (lane >= o) w += t;
        }
        ws[lane] = w;
    }
    __syncthreads();
    int excl = (x - v) + (wid > 0 ? ws[wid - 1] : 0);
    if (tid < SCAN_BLOCKS) g_blkoff[tid] = excl;
    if (tid == 0) g_rowoff[N_NODES] = N_EDGES;
}

__global__ void scan_p3_kernel() {
    int i = blockIdx.x * 256 + threadIdx.x;
    int v = (i < N_NODES) ? g_deg[i] : 0;
    int lane = threadIdx.x & 31, wid = threadIdx.x >> 5;
    int x = v;
#pragma unroll
    for (int o = 1; o < 32; o <<= 1) {
        int t = __shfl_up_sync(~0u, x, o);
        if (lane >= o) x += t;
    }
    __shared__ int ws[8];
    if (lane == 31) ws[wid] = x;
    __syncthreads();
    if (wid == 0 && lane < 8) {
        int w = ws[lane];
#pragma unroll
        for (int o = 1; o < 8; o <<= 1) {
            int t = __shfl_up_sync(0xffu, w, o);
            if (lane >= o) w += t;
        }
        ws[lane] = w;
    }
    __syncthreads();
    int excl = (x - v) + (wid > 0 ? ws[wid - 1] : 0) + g_blkoff[blockIdx.x];
    if (i < N_NODES) {
        g_rowoff[i] = excl;
        g_cursor[i] = excl;
    }
}

// scatter edges into CSR buckets (sorted by dst)
__global__ void fill_kernel() {
    int e = blockIdx.x * blockDim.x + threadIdx.x;
    if (e >= N_EDGES) return;
    int d = g_dst[e];
    int p = atomicAdd(&g_cursor[d], 1);
    g_srcS[p] = g_src[e];
    g_ewS[p] = g_ew[e];
}

// ---------------- gather-aggregate + fp16 split epilogue --------------------
// out_i = sum_{e: dst=i} in[src_e] * w_e ; emits fp16 hi / residual arrays.
template <int C, bool USE_W>
__global__ void gather_kernel(const float* __restrict__ in,
                              __half* __restrict__ outH,
                              __half* __restrict__ outL) {
    constexpr int L = C / 4;        // lanes per node
    constexpr int G = 256 / L;      // nodes per 256-thread block
    int grp  = threadIdx.x / L;
    int lane = threadIdx.x % L;
    int node = blockIdx.x * G + grp;
    if (node >= N_NODES) return;

    int e0 = g_rowoff[node];
    int e1 = g_rowoff[node + 1];
    const float4* in4 = (const float4*)in;
    float4 acc = make_float4(0.f, 0.f, 0.f, 0.f);

    int e = e0;
    for (; e + 4 <= e1; e += 4) {
        int s0 = g_srcS[e], s1 = g_srcS[e + 1];
        int s2 = g_srcS[e + 2], s3 = g_srcS[e + 3];
        float w0 = USE_W ? g_ewS[e] : 1.0f;
        float w1 = USE_W ? g_ewS[e + 1] : 1.0f;
        float w2 = USE_W ? g_ewS[e + 2] : 1.0f;
        float w3 = USE_W ? g_ewS[e + 3] : 1.0f;
        float4 v0 = in4[(size_t)s0 * L + lane];
        float4 v1 = in4[(size_t)s1 * L + lane];
        float4 v2 = in4[(size_t)s2 * L + lane];
        float4 v3 = in4[(size_t)s3 * L + lane];
        acc.x = fmaf(v0.x, w0, acc.x); acc.y = fmaf(v0.y, w0, acc.y);
        acc.z = fmaf(v0.z, w0, acc.z); acc.w = fmaf(v0.w, w0, acc.w);
        acc.x = fmaf(v1.x, w1, acc.x); acc.y = fmaf(v1.y, w1, acc.y);
        acc.z = fmaf(v1.z, w1, acc.z); acc.w = fmaf(v1.w, w1, acc.w);
        acc.x = fmaf(v2.x, w2, acc.x); acc.y = fmaf(v2.y, w2, acc.y);
        acc.z = fmaf(v2.z, w2, acc.z); acc.w = fmaf(v2.w, w2, acc.w);
        acc.x = fmaf(v3.x, w3, acc.x); acc.y = fmaf(v3.y, w3, acc.y);
        acc.z = fmaf(v3.z, w3, acc.z); acc.w = fmaf(v3.w, w3, acc.w);
    }
    for (; e < e1; e++) {
        int sa = g_srcS[e];
        float wa = USE_W ? g_ewS[e] : 1.0f;
        float4 va = in4[(size_t)sa * L + lane];
        acc.x = fmaf(va.x, wa, acc.x); acc.y = fmaf(va.y, wa, acc.y);
        acc.z = fmaf(va.z, wa, acc.z); acc.w = fmaf(va.w, wa, acc.w);
    }

    __half hx = __float2half_rn(acc.x);
    __half hy = __float2half_rn(acc.y);
    __half hz = __float2half_rn(acc.z);
    __half hw = __float2half_rn(acc.w);
    half2 hA = __halves2half2(hx, hy);
    half2 hB = __halves2half2(hz, hw);
    half2 lA = __halves2half2(__float2half_rn(acc.x - __half2float(hx)),
                              __float2half_rn(acc.y - __half2float(hy)));
    half2 lB = __halves2half2(__float2half_rn(acc.z - __half2float(hz)),
                              __float2half_rn(acc.w - __half2float(hw)));
    uint2 pH = make_uint2(h2_as_u32(hA), h2_as_u32(hB));
    uint2 pL = make_uint2(h2_as_u32(lA), h2_as_u32(lB));
    *(uint2*)(outH + (size_t)node * C + lane * 4) = pH;
    *(uint2*)(outL + (size_t)node * C + lane * 4) = pL;
}

// ---------------- tensor-core GEMM (fp16 split, pre-split operands) ---------
// out[M,256] = A @ W^T + epilogue.  BM=128, BN=64, BK=32, 256 threads =
// 8 warps (4m x 2n), warp tile 32x32 = 2 m-atoms x 4 n-atoms, m16n8k16.
// 3 terms per atom: Ah*Bh + Al*Bh + Ah*Bl (residuals ~2^-22, fp32 accum).
template <int K, bool BN_RELU>
__global__ void gemm_tc_kernel(const __half* __restrict__ Ah,
                               const __half* __restrict__ Al,
                               const __half* __restrict__ Bh,
                               const __half* __restrict__ Bl,
                               const float* __restrict__ bias,
                               const float* __restrict__ gam,
                               const float* __restrict__ bet,
                               const float* __restrict__ mu,
                               const float* __restrict__ var,
                               float* __restrict__ out) {
    constexpr int BM = 128, BN = 64, BK = 32;
    constexpr int PK = 20;  // row pitch in half2: g*20 mod 32 conflict-free
    __shared__ __align__(16) half2 sAh[BM][PK];
    __shared__ __align__(16) half2 sAl[BM][PK];
    __shared__ __align__(16) half2 sBh[BN][PK];
    __shared__ __align__(16) half2 sBl[BN][PK];

    int m0 = blockIdx.x * BM;
    int n0 = blockIdx.y * BN;
    int tid = threadIdx.x;
    int lane = tid & 31;
    int g = lane >> 2;        // 0..7
    int t = lane & 3;         // 0..3
    int wid = tid >> 5;       // 0..7
    int wm = wid & 3;         // warp m index (0..3)
    int wn = wid >> 2;        // warp n index (0..1)

    // loader mapping (halves)
    int arow = tid >> 1;            // 0..127
    int akq  = (tid & 1) * 16;      // 0 or 16
    int brow = tid >> 2;            // 0..63
    int bkq  = (tid & 3) * 8;       // 0,8,16,24

    float acc[2][4][4];
#pragma unroll
    for (int i = 0; i < 2; i++)
#pragma unroll
        for (int j = 0; j < 4; j++)
#pragma unroll
            for (int c = 0; c < 4; c++) acc[i][j][c] = 0.f;

    for (int kt = 0; kt < K; kt += BK) {
        // ---- A tiles (hi+lo): 2x uint4 loads per array per thread ----
        {
            int row = m0 + arow;
            uint4 h0 = make_uint4(0, 0, 0, 0), h1 = h0, l0 = h0, l1 = h0;
            if (row < N_NODES) {
                const __half* ap = Ah + (size_t)row * K + kt + akq;
                const __half* lp = Al + (size_t)row * K + kt + akq;
                h0 = *(const uint4*)(ap);
                h1 = *(const uint4*)(ap + 8);
                l0 = *(const uint4*)(lp);
                l1 = *(const uint4*)(lp + 8);
            }
            *(uint4*)&sAh[arow][akq / 2]     = h0;
            *(uint4*)&sAh[arow][akq / 2 + 4] = h1;
            *(uint4*)&sAl[arow][akq / 2]     = l0;
            *(uint4*)&sAl[arow][akq / 2 + 4] = l1;
        }
        // ---- B tiles (hi+lo): 1x uint4 per array per thread ----
        {
            const __half* bp = Bh + (size_t)(n0 + brow) * K + kt + bkq;
            const __half* lp = Bl + (size_t)(n0 + brow) * K + kt + bkq;
            *(uint4*)&sBh[brow][bkq / 2] = *(const uint4*)bp;
            *(uint4*)&sBl[brow][bkq / 2] = *(const uint4*)lp;
        }
        __syncthreads();

#pragma unroll
        for (int ko = 0; ko < 2; ko++) {   // two k16 steps per BK=32 tile
            int kb = ko * 8;               // half2 offset
            unsigned ah[2][4], al[2][4], bh[4][2], bl[4][2];
#pragma unroll
            for (int i = 0; i < 2; i++) {
                int rm = wm * 32 + i * 16;
                ah[i][0] = h2_as_u32(sAh[rm + g][kb + t]);
                ah[i][1] = h2_as_u32(sAh[rm + g + 8][kb + t]);
                ah[i][2] = h2_as_u32(sAh[rm + g][kb + t + 4]);
                ah[i][3] = h2_as_u32(sAh[rm + g + 8][kb + t + 4]);
                al[i][0] = h2_as_u32(sAl[rm + g][kb + t]);
                al[i][1] = h2_as_u32(sAl[rm + g + 8][kb + t]);
                al[i][2] = h2_as_u32(sAl[rm + g][kb + t + 4]);
                al[i][3] = h2_as_u32(sAl[rm + g + 8][kb + t + 4]);
            }
#pragma unroll
            for (int j = 0; j < 4; j++) {
                int cn = wn * 32 + j * 8;
                bh[j][0] = h2_as_u32(sBh[cn + g][kb + t]);
                bh[j][1] = h2_as_u32(sBh[cn + g][kb + t + 4]);
                bl[j][0] = h2_as_u32(sBl[cn + g][kb + t]);
                bl[j][1] = h2_as_u32(sBl[cn + g][kb + t + 4]);
            }
#pragma unroll
            for (int i = 0; i < 2; i++)
#pragma unroll
                for (int j = 0; j < 4; j++) {
                    mma_f16(acc[i][j], ah[i], bh[j]);
                    mma_f16(acc[i][j], al[i], bh[j]);
                    mma_f16(acc[i][j], ah[i], bl[j]);
                }
        }
        __syncthreads();
    }

    // ---- epilogue: +bias, optional BN(eval)+ReLU, float2 stores ----
#pragma unroll
    for (int j = 0; j < 4; j++) {
        int n = n0 + wn * 32 + j * 8 + 2 * t;
        float b0 = bias[n], b1 = bias[n + 1];
        float s0 = 0.f, s1 = 0.f, t0 = 0.f, t1 = 0.f;
        if (BN_RELU) {
            s0 = gam[n] * rsqrtf(var[n] + 1e-5f);
            t0 = bet[n] - mu[n] * s0;
            s1 = gam[n + 1] * rsqrtf(var[n + 1] + 1e-5f);
            t1 = bet[n + 1] - mu[n + 1] * s1;
        }
#pragma unroll
        for (int i = 0; i < 2; i++) {
            int r0 = m0 + wm * 32 + i * 16 + g;
            int r1 = r0 + 8;
            float z0 = acc[i][j][0] + b0;
            float z1 = acc[i][j][1] + b1;
            float z2 = acc[i][j][2] + b0;
            float z3 = acc[i][j][3] + b1;
            if (BN_RELU) {
                z0 = fmaxf(fmaf(z0, s0, t0), 0.f);
                z1 = fmaxf(fmaf(z1, s1, t1), 0.f);
                z2 = fmaxf(fmaf(z2, s0, t0), 0.f);
                z3 = fmaxf(fmaf(z3, s1, t1), 0.f);
            }
            if (r0 < N_NODES)
                *(float2*)(out + (size_t)r0 * C_OUT + n) = make_float2(z0, z1);
            if (r1 < N_NODES)
                *(float2*)(out + (size_t)r1 * C_OUT + n) = make_float2(z2, z3);
        }
    }
}

// ---------------- launch ----------------------------------------------------
extern "C" void kernel_launch(void* const* d_in, const int* in_sizes, int n_in,
                              void* d_out, int out_size) {
    const float* x   = (const float*)d_in[0];
    const int*   ei  = (const int*)d_in[1];
    const float* ea  = (const float*)d_in[2];
    const float* W1  = (const float*)d_in[3];
    const float* b1  = (const float*)d_in[4];
    const float* g1  = (const float*)d_in[5];
    const float* be1 = (const float*)d_in[6];
    const float* m1  = (const float*)d_in[7];
    const float* v1  = (const float*)d_in[8];
    const float* W2  = (const float*)d_in[9];
    const float* b2  = (const float*)d_in[10];
    const float* g2  = (const float*)d_in[11];
    const float* be2 = (const float*)d_in[12];
    const float* m2  = (const float*)d_in[13];
    const float* v2  = (const float*)d_in[14];
    const float* W3  = (const float*)d_in[15];
    const float* b3  = (const float*)d_in[16];
    float* out = (float*)d_out;

    void *p_aggH, *p_aggL, *p_h, *p_deg, *p_WH, *p_WL;
    cudaGetSymbolAddress(&p_aggH, g_aggH);
    cudaGetSymbolAddress(&p_aggL, g_aggL);
    cudaGetSymbolAddress(&p_h, g_h);
    cudaGetSymbolAddress(&p_deg, g_deg);
    cudaGetSymbolAddress(&p_WH, g_WH);
    cudaGetSymbolAddress(&p_WL, g_WL);
    __half* aggH = (__half*)p_aggH;
    __half* aggL = (__half*)p_aggL;
    float*  h    = (float*)p_h;
    __half* WH   = (__half*)p_WH;
    __half* WL   = (__half*)p_WL;
    const int offW2 = 256 * 128;
    const int offW3 = offW2 + 256 * 256;

    // ---- CSR build + weight split (once) ----
    detect_kernel<<<1, 64>>>(ei);
    cudaMemsetAsync(p_deg, 0, N_NODES * sizeof(int));
    build_edges_kernel<<<(N_EDGES + 255) / 256, 256>>>(ei, ea);
    split_w_kernel<<<(256 * 128 + 255) / 256, 256>>>(W1, 256 * 128, 0);
    split_w_kernel<<<(256 * 256 + 255) / 256, 256>>>(W2, 256 * 256, offW2);
    split_w_kernel<<<(256 * 256 + 255) / 256, 256>>>(W3, 256 * 256, offW3);
    scan_p1_kernel<<<SCAN_BLOCKS, 256>>>();
    scan_p2_kernel<<<1, 256>>>();
    scan_p3_kernel<<<SCAN_BLOCKS, 256>>>();
    fill_kernel<<<(N_EDGES + 255) / 256, 256>>>();

    dim3 ggrid((N_NODES + 127) / 128, 4);  // 391 x 4, BM=128 BN=64

    // ---- layer 1: aggregate x (C=128), GEMM K=128 + BN1 + ReLU ----
    gather_kernel<128, true><<<(N_NODES + 7) / 8, 256>>>(x, aggH, aggL);
    gemm_tc_kernel<128, true><<<ggrid, 256>>>(aggH, aggL, WH, WL,
                                              b1, g1, be1, m1, v1, h);

    // ---- layer 2: aggregate h (C=256), GEMM K=256 + BN2 + ReLU ----
    gather_kernel<256, true><<<(N_NODES + 3) / 4, 256>>>(h, aggH, aggL);
    gemm_tc_kernel<256, true><<<ggrid, 256>>>(aggH, aggL, WH + offW2, WL + offW2,
                                              b2, g2, be2, m2, v2, h);

    // ---- layer 3: aggregate h (C=256, no edge weight), GEMM K=256 + bias ----
    gather_kernel<256, false><<<(N_NODES + 3) / 4, 256>>>(h, aggH, aggL);
    gemm_tc_kernel<256, false><<<ggrid, 256>>>(aggH, aggL, WH + offW3, WL + offW3,
                                               b3, nullptr, nullptr, nullptr,
                                               nullptr, out);
}

// round 9
// speedup vs baseline: 1.6912x; 1.1408x over previous
#include <cuda_runtime.h>
#include <cuda_fp16.h>

#define N_NODES 50000
#define N_EDGES 1600000
#define C_OUT   256
#define SCAN_BLOCKS 196   // ceil(50000/256)
#define W_TOTAL (256*128 + 256*256 + 256*256)

// ---------------- scratch (static device globals; allocation-free) ----------
__device__ int    g_is64;
__device__ int    g_src[N_EDGES];
__device__ int    g_dst[N_EDGES];
__device__ float  g_ew[N_EDGES];
__device__ int    g_srcS[N_EDGES];
__device__ float  g_ewS[N_EDGES];
__device__ int    g_deg[N_NODES];
__device__ int    g_blkoff[SCAN_BLOCKS];
__device__ int    g_rowoff[N_NODES + 1];
__device__ int    g_cursor[N_NODES];
__device__ __half g_xh[(size_t)N_NODES * 128];       // fp16 copy of input x
__device__ __half g_hf[(size_t)N_NODES * C_OUT];     // fp16 hidden activations
__device__ __half g_aggH[(size_t)N_NODES * C_OUT];   // fp16 hi of aggregate
__device__ __half g_aggL[(size_t)N_NODES * C_OUT];   // fp16 residual
__device__ __half g_WH[W_TOTAL];
__device__ __half g_WL[W_TOTAL];

__device__ __forceinline__ unsigned h2_as_u32(half2 v) {
    unsigned u;
    memcpy(&u, &v, 4);
    return u;
}

// d(16x8 f32) += A(16x16 f16) * B(16x8 f16)
__device__ __forceinline__ void mma_f16(float c[4], const unsigned a[4],
                                        const unsigned b[2]) {
    asm("mma.sync.aligned.m16n8k16.row.col.f32.f16.f16.f32 "
        "{%0,%1,%2,%3}, {%4,%5,%6,%7}, {%8,%9}, {%0,%1,%2,%3};"
        : "+f"(c[0]), "+f"(c[1]), "+f"(c[2]), "+f"(c[3])
        : "r"(a[0]), "r"(a[1]), "r"(a[2]), "r"(a[3]), "r"(b[0]), "r"(b[1]));
}

// ---------------- int64-vs-int32 edge_index detection -----------------------
__global__ void detect_kernel(const int* __restrict__ ei_words) {
    __shared__ int nz;
    if (threadIdx.x == 0) nz = 0;
    __syncthreads();
    if (ei_words[2 * threadIdx.x + 1] != 0) atomicOr(&nz, 1);
    __syncthreads();
    if (threadIdx.x == 0) g_is64 = (nz == 0) ? 1 : 0;
}

// split a weight blob into fp16 hi / fp16 residual (once per launch)
__global__ void split_w_kernel(const float* __restrict__ src, int n, int off) {
    int i = blockIdx.x * blockDim.x + threadIdx.x;
    if (i >= n) return;
    float v = src[i];
    __half h = __float2half_rn(v);
    g_WH[off + i] = h;
    g_WL[off + i] = __float2half_rn(v - __half2float(h));
}

// convert input x to fp16 (once per launch)
__global__ void x2h_kernel(const float* __restrict__ x) {
    int i = blockIdx.x * blockDim.x + threadIdx.x;
    if (i >= N_NODES * 128 / 4) return;
    float4 v = ((const float4*)x)[i];
    half2 a = __halves2half2(__float2half_rn(v.x), __float2half_rn(v.y));
    half2 b = __halves2half2(__float2half_rn(v.z), __float2half_rn(v.w));
    ((uint2*)g_xh)[i] = make_uint2(h2_as_u32(a), h2_as_u32(b));
}

// decode edge_index, compute ew = mean(edge_attr, -1), histogram dst degrees
__global__ void build_edges_kernel(const int* __restrict__ ei,
                                   const float* __restrict__ ea) {
    int e = blockIdx.x * blockDim.x + threadIdx.x;
    if (e >= N_EDGES) return;
    int s, d;
    if (g_is64) {
        s = ei[2 * (size_t)e];
        d = ei[2 * (size_t)N_EDGES + 2 * (size_t)e];
    } else {
        s = ei[e];
        d = ei[N_EDGES + e];
    }
    g_src[e] = s;
    g_dst[e] = d;
    const float4* a4 = (const float4*)(ea + (size_t)e * 8);
    float4 u = a4[0];
    float4 v = a4[1];
    g_ew[e] = (u.x + u.y + u.z + u.w + v.x + v.y + v.z + v.w) * 0.125f;
    atomicAdd(&g_deg[d], 1);
}

// ---------------- decoupled 3-phase exclusive scan ---------------------------
__global__ void scan_p1_kernel() {
    int i = blockIdx.x * 256 + threadIdx.x;
    int v = (i < N_NODES) ? g_deg[i] : 0;
#pragma unroll
    for (int o = 16; o > 0; o >>= 1) v += __shfl_down_sync(~0u, v, o);
    __shared__ int ws[8];
    int lane = threadIdx.x & 31, wid = threadIdx.x >> 5;
    if (lane == 0) ws[wid] = v;
    __syncthreads();
    if (threadIdx.x == 0) {
        int s = 0;
#pragma unroll
        for (int w = 0; w < 8; w++) s += ws[w];
        g_blkoff[blockIdx.x] = s;
    }
}

__global__ void scan_p2_kernel() {
    int tid = threadIdx.x;  // 256 threads
    int v = (tid < SCAN_BLOCKS) ? g_blkoff[tid] : 0;
    int lane = tid & 31, wid = tid >> 5;
    int x = v;
#pragma unroll
    for (int o = 1; o < 32; o <<= 1) {
        int t = __shfl_up_sync(~0u, x, o);
        if (lane >= o) x += t;
    }
    __shared__ int ws[8];
    if (lane == 31) ws[wid] = x;
    __syncthreads();
    if (wid == 0 && lane < 8) {
        int w = ws[lane];
#pragma unroll
        for (int o = 1; o < 8; o <<= 1) {
            int t = __shfl_up_sync(0xffu, w, o);
            if (lane >= o) w += t;
        }
        ws[lane] = w;
    }
    __syncthreads();
    int excl = (x - v) + (wid > 0 ? ws[wid - 1] : 0);
    if (tid < SCAN_BLOCKS) g_blkoff[tid] = excl;
    if (tid == 0) g_rowoff[N_NODES] = N_EDGES;
}

__global__ void scan_p3_kernel() {
    int i = blockIdx.x * 256 + threadIdx.x;
    int v = (i < N_NODES) ? g_deg[i] : 0;
    int lane = threadIdx.x & 31, wid = threadIdx.x >> 5;
    int x = v;
#pragma unroll
    for (int o = 1; o < 32; o <<= 1) {
        int t = __shfl_up_sync(~0u, x, o);
        if (lane >= o) x += t;
    }
    __shared__ int ws[8];
    if (lane == 31) ws[wid] = x;
    __syncthreads();
    if (wid == 0 && lane < 8) {
        int w = ws[lane];
#pragma unroll
        for (int o = 1; o < 8; o <<= 1) {
            int t = __shfl_up_sync(0xffu, w, o);
            if (lane >= o) w += t;
        }
        ws[lane] = w;
    }
    __syncthreads();
    int excl = (x - v) + (wid > 0 ? ws[wid - 1] : 0) + g_blkoff[blockIdx.x];
    if (i < N_NODES) {
        g_rowoff[i] = excl;
        g_cursor[i] = excl;
    }
}

// scatter edges into CSR buckets (sorted by dst)
__global__ void fill_kernel() {
    int e = blockIdx.x * blockDim.x + threadIdx.x;
    if (e >= N_EDGES) return;
    int d = g_dst[e];
    int p = atomicAdd(&g_cursor[d], 1);
    g_srcS[p] = g_src[e];
    g_ewS[p] = g_ew[e];
}

// ---------------- gather-aggregate (fp16 rows) + fp16 split epilogue --------
// out_i = sum_{e: dst=i} in[src_e] * w_e ; in is fp16, acc fp32, out hi/lo.
// Each lane owns 8 channels: one uint4 (16B) per gathered row.
template <int C, bool USE_W>
__global__ void gather_kernel(const __half* __restrict__ in,
                              __half* __restrict__ outH,
                              __half* __restrict__ outL) {
    constexpr int L = C / 8;        // lanes per node (16 or 32)
    constexpr int G = 256 / L;      // nodes per 256-thread block
    int grp  = threadIdx.x / L;
    int lane = threadIdx.x % L;
    int node = blockIdx.x * G + grp;
    if (node >= N_NODES) return;

    int e0 = g_rowoff[node];
    int e1 = g_rowoff[node + 1];
    const uint4* in4 = (const uint4*)in;   // row stride = C/8 uint4
    float acc[8];
#pragma unroll
    for (int q = 0; q < 8; q++) acc[q] = 0.f;

    int e = e0;
    for (; e + 4 <= e1; e += 4) {
        int   s[4];
        float w[4];
#pragma unroll
        for (int u = 0; u < 4; u++) {
            s[u] = g_srcS[e + u];
            w[u] = USE_W ? g_ewS[e + u] : 1.0f;
        }
#pragma unroll
        for (int u = 0; u < 4; u++) {
            uint4 r = in4[(size_t)s[u] * L + lane];
            half2 h0 = *(half2*)&r.x, h1 = *(half2*)&r.y;
            half2 h2 = *(half2*)&r.z, h3 = *(half2*)&r.w;
            float2 f0 = __half22float2(h0), f1 = __half22float2(h1);
            float2 f2 = __half22float2(h2), f3 = __half22float2(h3);
            acc[0] = fmaf(f0.x, w[u], acc[0]); acc[1] = fmaf(f0.y, w[u], acc[1]);
            acc[2] = fmaf(f1.x, w[u], acc[2]); acc[3] = fmaf(f1.y, w[u], acc[3]);
            acc[4] = fmaf(f2.x, w[u], acc[4]); acc[5] = fmaf(f2.y, w[u], acc[5]);
            acc[6] = fmaf(f3.x, w[u], acc[6]); acc[7] = fmaf(f3.y, w[u], acc[7]);
        }
    }
    for (; e < e1; e++) {
        int sa = g_srcS[e];
        float wa = USE_W ? g_ewS[e] : 1.0f;
        uint4 r = in4[(size_t)sa * L + lane];
        half2 h0 = *(half2*)&r.x, h1 = *(half2*)&r.y;
        half2 h2 = *(half2*)&r.z, h3 = *(half2*)&r.w;
        float2 f0 = __half22float2(h0), f1 = __half22float2(h1);
        float2 f2 = __half22float2(h2), f3 = __half22float2(h3);
        acc[0] = fmaf(f0.x, wa, acc[0]); acc[1] = fmaf(f0.y, wa, acc[1]);
        acc[2] = fmaf(f1.x, wa, acc[2]); acc[3] = fmaf(f1.y, wa, acc[3]);
        acc[4] = fmaf(f2.x, wa, acc[4]); acc[5] = fmaf(f2.y, wa, acc[5]);
        acc[6] = fmaf(f3.x, wa, acc[6]); acc[7] = fmaf(f3.y, wa, acc[7]);
    }

    // fp16 hi/lo split of the fp32 accumulator
    half2 hh[4], ll[4];
#pragma unroll
    for (int q = 0; q < 4; q++) {
        __half a = __float2half_rn(acc[2 * q]);
        __half b = __float2half_rn(acc[2 * q + 1]);
        hh[q] = __halves2half2(a, b);
        ll[q] = __halves2half2(
            __float2half_rn(acc[2 * q] - __half2float(a)),
            __float2half_rn(acc[2 * q + 1] - __half2float(b)));
    }
    uint4 pH = make_uint4(h2_as_u32(hh[0]), h2_as_u32(hh[1]),
                          h2_as_u32(hh[2]), h2_as_u32(hh[3]));
    uint4 pL = make_uint4(h2_as_u32(ll[0]), h2_as_u32(ll[1]),
                          h2_as_u32(ll[2]), h2_as_u32(ll[3]));
    *(uint4*)(outH + (size_t)node * C + lane * 8) = pH;
    *(uint4*)(outL + (size_t)node * C + lane * 8) = pL;
}

// ---------------- tensor-core GEMM (fp16 split, pre-split operands) ---------
// out[M,256] = A @ W^T + epilogue.  BM=128, BN=64, BK=32, 256 threads =
// 8 warps (4m x 2n), warp tile 32x32 = 2 m-atoms x 4 n-atoms, m16n8k16.
// 3 terms per atom: Ah*Bh + Al*Bh + Ah*Bl. OUT_HALF: write fp16 activations.
template <int K, bool BN_RELU, bool OUT_HALF>
__global__ void gemm_tc_kernel(const __half* __restrict__ Ah,
                               const __half* __restrict__ Al,
                               const __half* __restrict__ Bh,
                               const __half* __restrict__ Bl,
                               const float* __restrict__ bias,
                               const float* __restrict__ gam,
                               const float* __restrict__ bet,
                               const float* __restrict__ mu,
                               const float* __restrict__ var,
                               void* __restrict__ out_v) {
    constexpr int BM = 128, BN = 64, BK = 32;
    constexpr int PK = 20;  // row pitch in half2: conflict-free frag LDS
    __shared__ __align__(16) half2 sAh[BM][PK];
    __shared__ __align__(16) half2 sAl[BM][PK];
    __shared__ __align__(16) half2 sBh[BN][PK];
    __shared__ __align__(16) half2 sBl[BN][PK];

    int m0 = blockIdx.x * BM;
    int n0 = blockIdx.y * BN;
    int tid = threadIdx.x;
    int lane = tid & 31;
    int g = lane >> 2;        // 0..7
    int t = lane & 3;         // 0..3
    int wid = tid >> 5;       // 0..7
    int wm = wid & 3;         // warp m index (0..3)
    int wn = wid >> 2;        // warp n index (0..1)

    int arow = tid >> 1;            // 0..127
    int akq  = (tid & 1) * 16;      // 0 or 16
    int brow = tid >> 2;            // 0..63
    int bkq  = (tid & 3) * 8;       // 0,8,16,24

    float acc[2][4][4];
#pragma unroll
    for (int i = 0; i < 2; i++)
#pragma unroll
        for (int j = 0; j < 4; j++)
#pragma unroll
            for (int c = 0; c < 4; c++) acc[i][j][c] = 0.f;

    for (int kt = 0; kt < K; kt += BK) {
        {
            int row = m0 + arow;
            uint4 h0 = make_uint4(0, 0, 0, 0), h1 = h0, l0 = h0, l1 = h0;
            if (row < N_NODES) {
                const __half* ap = Ah + (size_t)row * K + kt + akq;
                const __half* lp = Al + (size_t)row * K + kt + akq;
                h0 = *(const uint4*)(ap);
                h1 = *(const uint4*)(ap + 8);
                l0 = *(const uint4*)(lp);
                l1 = *(const uint4*)(lp + 8);
            }
            *(uint4*)&sAh[arow][akq / 2]     = h0;
            *(uint4*)&sAh[arow][akq / 2 + 4] = h1;
            *(uint4*)&sAl[arow][akq / 2]     = l0;
            *(uint4*)&sAl[arow][akq / 2 + 4] = l1;
        }
        {
            const __half* bp = Bh + (size_t)(n0 + brow) * K + kt + bkq;
            const __half* lp = Bl + (size_t)(n0 + brow) * K + kt + bkq;
            *(uint4*)&sBh[brow][bkq / 2] = *(const uint4*)bp;
            *(uint4*)&sBl[brow][bkq / 2] = *(const uint4*)lp;
        }
        __syncthreads();

#pragma unroll
        for (int ko = 0; ko < 2; ko++) {   // two k16 steps per BK=32 tile
            int kb = ko * 8;               // half2 offset
            unsigned ah[2][4], al[2][4], bh[4][2], bl[4][2];
#pragma unroll
            for (int i = 0; i < 2; i++) {
                int rm = wm * 32 + i * 16;
                ah[i][0] = h2_as_u32(sAh[rm + g][kb + t]);
                ah[i][1] = h2_as_u32(sAh[rm + g + 8][kb + t]);
                ah[i][2] = h2_as_u32(sAh[rm + g][kb + t + 4]);
                ah[i][3] = h2_as_u32(sAh[rm + g + 8][kb + t + 4]);
                al[i][0] = h2_as_u32(sAl[rm + g][kb + t]);
                al[i][1] = h2_as_u32(sAl[rm + g + 8][kb + t]);
                al[i][2] = h2_as_u32(sAl[rm + g][kb + t + 4]);
                al[i][3] = h2_as_u32(sAl[rm + g + 8][kb + t + 4]);
            }
#pragma unroll
            for (int j = 0; j < 4; j++) {
                int cn = wn * 32 + j * 8;
                bh[j][0] = h2_as_u32(sBh[cn + g][kb + t]);
                bh[j][1] = h2_as_u32(sBh[cn + g][kb + t + 4]);
                bl[j][0] = h2_as_u32(sBl[cn + g][kb + t]);
                bl[j][1] = h2_as_u32(sBl[cn + g][kb + t + 4]);
            }
#pragma unroll
            for (int i = 0; i < 2; i++)
#pragma unroll
                for (int j = 0; j < 4; j++) {
                    mma_f16(acc[i][j], ah[i], bh[j]);
                    mma_f16(acc[i][j], al[i], bh[j]);
                    mma_f16(acc[i][j], ah[i], bl[j]);
                }
        }
        __syncthreads();
    }

    // ---- epilogue: +bias, optional BN(eval)+ReLU ----
#pragma unroll
    for (int j = 0; j < 4; j++) {
        int n = n0 + wn * 32 + j * 8 + 2 * t;
        float b0 = bias[n], b1 = bias[n + 1];
        float s0 = 0.f, s1 = 0.f, t0 = 0.f, t1 = 0.f;
        if (BN_RELU) {
            s0 = gam[n] * rsqrtf(var[n] + 1e-5f);
            t0 = bet[n] - mu[n] * s0;
            s1 = gam[n + 1] * rsqrtf(var[n + 1] + 1e-5f);
            t1 = bet[n + 1] - mu[n + 1] * s1;
        }
#pragma unroll
        for (int i = 0; i < 2; i++) {
            int r0 = m0 + wm * 32 + i * 16 + g;
            int r1 = r0 + 8;
            float z0 = acc[i][j][0] + b0;
            float z1 = acc[i][j][1] + b1;
            float z2 = acc[i][j][2] + b0;
            float z3 = acc[i][j][3] + b1;
            if (BN_RELU) {
                z0 = fmaxf(fmaf(z0, s0, t0), 0.f);
                z1 = fmaxf(fmaf(z1, s1, t1), 0.f);
                z2 = fmaxf(fmaf(z2, s0, t0), 0.f);
                z3 = fmaxf(fmaf(z3, s1, t1), 0.f);
            }
            if (OUT_HALF) {
                __half* oh = (__half*)out_v;
                half2 p0 = __halves2half2(__float2half_rn(z0), __float2half_rn(z1));
                half2 p1 = __halves2half2(__float2half_rn(z2), __float2half_rn(z3));
                if (r0 < N_NODES)
                    *(half2*)(oh + (size_t)r0 * C_OUT + n) = p0;
                if (r1 < N_NODES)
                    *(half2*)(oh + (size_t)r1 * C_OUT + n) = p1;
            } else {
                float* of = (float*)out_v;
                if (r0 < N_NODES)
                    *(float2*)(of + (size_t)r0 * C_OUT + n) = make_float2(z0, z1);
                if (r1 < N_NODES)
                    *(float2*)(of + (size_t)r1 * C_OUT + n) = make_float2(z2, z3);
            }
        }
    }
}

// ---------------- launch ----------------------------------------------------
extern "C" void kernel_launch(void* const* d_in, const int* in_sizes, int n_in,
                              void* d_out, int out_size) {
    const float* x   = (const float*)d_in[0];
    const int*   ei  = (const int*)d_in[1];
    const float* ea  = (const float*)d_in[2];
    const float* W1  = (const float*)d_in[3];
    const float* b1  = (const float*)d_in[4];
    const float* g1  = (const float*)d_in[5];
    const float* be1 = (const float*)d_in[6];
    const float* m1  = (const float*)d_in[7];
    const float* v1  = (const float*)d_in[8];
    const float* W2  = (const float*)d_in[9];
    const float* b2  = (const float*)d_in[10];
    const float* g2  = (const float*)d_in[11];
    const float* be2 = (const float*)d_in[12];
    const float* m2  = (const float*)d_in[13];
    const float* v2  = (const float*)d_in[14];
    const float* W3  = (const float*)d_in[15];
    const float* b3  = (const float*)d_in[16];

    void *p_aggH, *p_aggL, *p_hf, *p_xh, *p_deg, *p_WH, *p_WL;
    cudaGetSymbolAddress(&p_aggH, g_aggH);
    cudaGetSymbolAddress(&p_aggL, g_aggL);
    cudaGetSymbolAddress(&p_hf, g_hf);
    cudaGetSymbolAddress(&p_xh, g_xh);
    cudaGetSymbolAddress(&p_deg, g_deg);
    cudaGetSymbolAddress(&p_WH, g_WH);
    cudaGetSymbolAddress(&p_WL, g_WL);
    __half* aggH = (__half*)p_aggH;
    __half* aggL = (__half*)p_aggL;
    __half* hf   = (__half*)p_hf;
    __half* xh   = (__half*)p_xh;
    __half* WH   = (__half*)p_WH;
    __half* WL   = (__half*)p_WL;
    const int offW2 = 256 * 128;
    const int offW3 = offW2 + 256 * 256;

    // ---- CSR build + weight/x conversion (once) ----
    detect_kernel<<<1, 64>>>(ei);
    cudaMemsetAsync(p_deg, 0, N_NODES * sizeof(int));
    build_edges_kernel<<<(N_EDGES + 255) / 256, 256>>>(ei, ea);
    split_w_kernel<<<(256 * 128 + 255) / 256, 256>>>(W1, 256 * 128, 0);
    split_w_kernel<<<(256 * 256 + 255) / 256, 256>>>(W2, 256 * 256, offW2);
    split_w_kernel<<<(256 * 256 + 255) / 256, 256>>>(W3, 256 * 256, offW3);
    x2h_kernel<<<(N_NODES * 128 / 4 + 255) / 256, 256>>>(x);
    scan_p1_kernel<<<SCAN_BLOCKS, 256>>>();
    scan_p2_kernel<<<1, 256>>>();
    scan_p3_kernel<<<SCAN_BLOCKS, 256>>>();
    fill_kernel<<<(N_EDGES + 255) / 256, 256>>>();

    dim3 ggrid((N_NODES + 127) / 128, 4);  // 391 x 4, BM=128 BN=64

    // ---- layer 1: gather x_fp16 (C=128), GEMM K=128 + BN1 + ReLU -> fp16 h --
    gather_kernel<128, true><<<(N_NODES + 15) / 16, 256>>>(xh, aggH, aggL);
    gemm_tc_kernel<128, true, true><<<ggrid, 256>>>(aggH, aggL, WH, WL,
                                                    b1, g1, be1, m1, v1, hf);

    // ---- layer 2: gather h_fp16 (C=256), GEMM K=256 + BN2 + ReLU -> fp16 h --
    gather_kernel<256, true><<<(N_NODES + 7) / 8, 256>>>(hf, aggH, aggL);
    gemm_tc_kernel<256, true, true><<<ggrid, 256>>>(aggH, aggL,
                                                    WH + offW2, WL + offW2,
                                                    b2, g2, be2, m2, v2, hf);

    // ---- layer 3: gather h_fp16 (C=256, no weight), GEMM + bias -> fp32 out -
    gather_kernel<256, false><<<(N_NODES + 7) / 8, 256>>>(hf, aggH, aggL);
    gemm_tc_kernel<256, false, false><<<ggrid, 256>>>(aggH, aggL,
                                                      WH + offW3, WL + offW3,
                                                      b3, nullptr, nullptr,
                                                      nullptr, nullptr, d_out);
}

// round 10
// speedup vs baseline: 2.0770x; 1.2282x over previous
#include <cuda_runtime.h>
#include <cuda_fp16.h>

#define N_NODES 50000
#define N_EDGES 1600000
#define C_OUT   256
#define SCAN_BLOCKS 196   // ceil(50000/256)
#define W1_N (256*128)
#define W2_N (256*256)
#define W_TOTAL (W1_N + 2*W2_N)

// ---------------- scratch (static device globals; allocation-free) ----------
__device__ int    g_is64;
__device__ int    g_srcS[N_EDGES];
__device__ float  g_ewS[N_EDGES];
__device__ int    g_deg[N_NODES];
__device__ int    g_blkoff[SCAN_BLOCKS];
__device__ int    g_rowoff[N_NODES + 1];
__device__ int    g_cursor[N_NODES];
__device__ __half g_xh[(size_t)N_NODES * 128];       // fp16 copy of input x
__device__ __half g_hf[(size_t)N_NODES * C_OUT];     // fp16 hidden activations
__device__ __half g_agg[(size_t)N_NODES * C_OUT];    // fp16 aggregate
__device__ __half g_WH[W_TOTAL];
__device__ __half g_WL[W_TOTAL];

__device__ __forceinline__ unsigned h2_as_u32(half2 v) {
    unsigned u;
    memcpy(&u, &v, 4);
    return u;
}

// d(16x8 f32) += A(16x16 f16) * B(16x8 f16)
__device__ __forceinline__ void mma_f16(float c[4], const unsigned a[4],
                                        const unsigned b[2]) {
    asm("mma.sync.aligned.m16n8k16.row.col.f32.f16.f16.f32 "
        "{%0,%1,%2,%3}, {%4,%5,%6,%7}, {%8,%9}, {%0,%1,%2,%3};"
        : "+f"(c[0]), "+f"(c[1]), "+f"(c[2]), "+f"(c[3])
        : "r"(a[0]), "r"(a[1]), "r"(a[2]), "r"(a[3]), "r"(b[0]), "r"(b[1]));
}

// ---------------- int64-vs-int32 edge_index detection -----------------------
__global__ void detect_kernel(const int* __restrict__ ei_words) {
    __shared__ int nz;
    if (threadIdx.x == 0) nz = 0;
    __syncthreads();
    if (ei_words[2 * threadIdx.x + 1] != 0) atomicOr(&nz, 1);
    __syncthreads();
    if (threadIdx.x == 0) g_is64 = (nz == 0) ? 1 : 0;
}

// split all three weight blobs into fp16 hi / residual (one kernel)
__global__ void split_w_kernel(const float* __restrict__ W1,
                               const float* __restrict__ W2,
                               const float* __restrict__ W3) {
    int i = blockIdx.x * blockDim.x + threadIdx.x;
    if (i >= W_TOTAL) return;
    float v;
    if (i < W1_N)               v = W1[i];
    else if (i < W1_N + W2_N)   v = W2[i - W1_N];
    else                        v = W3[i - W1_N - W2_N];
    __half h = __float2half_rn(v);
    g_WH[i] = h;
    g_WL[i] = __float2half_rn(v - __half2float(h));
}

// convert input x to fp16 (once per launch)
__global__ void x2h_kernel(const float* __restrict__ x) {
    int i = blockIdx.x * blockDim.x + threadIdx.x;
    if (i >= N_NODES * 128 / 4) return;
    float4 v = ((const float4*)x)[i];
    half2 a = __halves2half2(__float2half_rn(v.x), __float2half_rn(v.y));
    half2 b = __halves2half2(__float2half_rn(v.z), __float2half_rn(v.w));
    ((uint2*)g_xh)[i] = make_uint2(h2_as_u32(a), h2_as_u32(b));
}

// histogram dst degrees straight from edge_index
__global__ void hist_kernel(const int* __restrict__ ei) {
    int e = blockIdx.x * blockDim.x + threadIdx.x;
    if (e >= N_EDGES) return;
    int d = g_is64 ? ei[2 * (size_t)N_EDGES + 2 * (size_t)e]
                   : ei[N_EDGES + e];
    atomicAdd(&g_deg[d], 1);
}

// ---------------- decoupled 3-phase exclusive scan ---------------------------
__global__ void scan_p1_kernel() {
    int i = blockIdx.x * 256 + threadIdx.x;
    int v = (i < N_NODES) ? g_deg[i] : 0;
#pragma unroll
    for (int o = 16; o > 0; o >>= 1) v += __shfl_down_sync(~0u, v, o);
    __shared__ int ws[8];
    int lane = threadIdx.x & 31, wid = threadIdx.x >> 5;
    if (lane == 0) ws[wid] = v;
    __syncthreads();
    if (threadIdx.x == 0) {
        int s = 0;
#pragma unroll
        for (int w = 0; w < 8; w++) s += ws[w];
        g_blkoff[blockIdx.x] = s;
    }
}

__global__ void scan_p2_kernel() {
    int tid = threadIdx.x;  // 256 threads
    int v = (tid < SCAN_BLOCKS) ? g_blkoff[tid] : 0;
    int lane = tid & 31, wid = tid >> 5;
    int x = v;
#pragma unroll
    for (int o = 1; o < 32; o <<= 1) {
        int t = __shfl_up_sync(~0u, x, o);
        if (lane >= o) x += t;
    }
    __shared__ int ws[8];
    if (lane == 31) ws[wid] = x;
    __syncthreads();
    if (wid == 0 && lane < 8) {
        int w = ws[lane];
#pragma unroll
        for (int o = 1; o < 8; o <<= 1) {
            int t = __shfl_up_sync(0xffu, w, o);
            if (lane >= o) w += t;
        }
        ws[lane] = w;
    }
    __syncthreads();
    int excl = (x - v) + (wid > 0 ? ws[wid - 1] : 0);
    if (tid < SCAN_BLOCKS) g_blkoff[tid] = excl;
    if (tid == 0) g_rowoff[N_NODES] = N_EDGES;
}

__global__ void scan_p3_kernel() {
    int i = blockIdx.x * 256 + threadIdx.x;
    int v = (i < N_NODES) ? g_deg[i] : 0;
    int lane = threadIdx.x & 31, wid = threadIdx.x >> 5;
    int x = v;
#pragma unroll
    for (int o = 1; o < 32; o <<= 1) {
        int t = __shfl_up_sync(~0u, x, o);
        if (lane >= o) x += t;
    }
    __shared__ int ws[8];
    if (lane == 31) ws[wid] = x;
    __syncthreads();
    if (wid == 0 && lane < 8) {
        int w = ws[lane];
#pragma unroll
        for (int o = 1; o < 8; o <<= 1) {
            int t = __shfl_up_sync(0xffu, w, o);
            if (lane >= o) w += t;
        }
        ws[lane] = w;
    }
    __syncthreads();
    int excl = (x - v) + (wid > 0 ? ws[wid - 1] : 0) + g_blkoff[blockIdx.x];
    if (i < N_NODES) {
        g_rowoff[i] = excl;
        g_cursor[i] = excl;
    }
}

// decode edge, compute ew = mean(edge_attr,-1), scatter into CSR buckets
__global__ void fill_kernel(const int* __restrict__ ei,
                            const float* __restrict__ ea) {
    int e = blockIdx.x * blockDim.x + threadIdx.x;
    if (e >= N_EDGES) return;
    int s, d;
    if (g_is64) {
        s = ei[2 * (size_t)e];
        d = ei[2 * (size_t)N_EDGES + 2 * (size_t)e];
    } else {
        s = ei[e];
        d = ei[N_EDGES + e];
    }
    const float4* a4 = (const float4*)(ea + (size_t)e * 8);
    float4 u = a4[0];
    float4 v = a4[1];
    float ew = (u.x + u.y + u.z + u.w + v.x + v.y + v.z + v.w) * 0.125f;
    int p = atomicAdd(&g_cursor[d], 1);
    g_srcS[p] = s;
    g_ewS[p] = ew;
}

// ---------------- gather-aggregate (fp16 rows -> fp16 aggregate) ------------
// out_i = sum_{e: dst=i} in[src_e] * w_e ; fp32 accum, fp16 store.
// Each lane owns 8 channels: one uint4 (16B) per gathered row.
template <int C, bool USE_W>
__global__ void gather_kernel(const __half* __restrict__ in,
                              __half* __restrict__ out) {
    constexpr int L = C / 8;        // lanes per node (16 or 32)
    constexpr int G = 256 / L;      // nodes per 256-thread block
    int grp  = threadIdx.x / L;
    int lane = threadIdx.x % L;
    int node = blockIdx.x * G + grp;
    if (node >= N_NODES) return;

    int e0 = g_rowoff[node];
    int e1 = g_rowoff[node + 1];
    const uint4* in4 = (const uint4*)in;   // row stride = C/8 uint4
    float acc[8];
#pragma unroll
    for (int q = 0; q < 8; q++) acc[q] = 0.f;

    int e = e0;
    for (; e + 4 <= e1; e += 4) {
        int   s[4];
        float w[4];
#pragma unroll
        for (int u = 0; u < 4; u++) {
            s[u] = g_srcS[e + u];
            w[u] = USE_W ? g_ewS[e + u] : 1.0f;
        }
#pragma unroll
        for (int u = 0; u < 4; u++) {
            uint4 r = in4[(size_t)s[u] * L + lane];
            half2 h0 = *(half2*)&r.x, h1 = *(half2*)&r.y;
            half2 h2 = *(half2*)&r.z, h3 = *(half2*)&r.w;
            float2 f0 = __half22float2(h0), f1 = __half22float2(h1);
            float2 f2 = __half22float2(h2), f3 = __half22float2(h3);
            acc[0] = fmaf(f0.x, w[u], acc[0]); acc[1] = fmaf(f0.y, w[u], acc[1]);
            acc[2] = fmaf(f1.x, w[u], acc[2]); acc[3] = fmaf(f1.y, w[u], acc[3]);
            acc[4] = fmaf(f2.x, w[u], acc[4]); acc[5] = fmaf(f2.y, w[u], acc[5]);
            acc[6] = fmaf(f3.x, w[u], acc[6]); acc[7] = fmaf(f3.y, w[u], acc[7]);
        }
    }
    for (; e < e1; e++) {
        int sa = g_srcS[e];
        float wa = USE_W ? g_ewS[e] : 1.0f;
        uint4 r = in4[(size_t)sa * L + lane];
        half2 h0 = *(half2*)&r.x, h1 = *(half2*)&r.y;
        half2 h2 = *(half2*)&r.z, h3 = *(half2*)&r.w;
        float2 f0 = __half22float2(h0), f1 = __half22float2(h1);
        float2 f2 = __half22float2(h2), f3 = __half22float2(h3);
        acc[0] = fmaf(f0.x, wa, acc[0]); acc[1] = fmaf(f0.y, wa, acc[1]);
        acc[2] = fmaf(f1.x, wa, acc[2]); acc[3] = fmaf(f1.y, wa, acc[3]);
        acc[4] = fmaf(f2.x, wa, acc[4]); acc[5] = fmaf(f2.y, wa, acc[5]);
        acc[6] = fmaf(f3.x, wa, acc[6]); acc[7] = fmaf(f3.y, wa, acc[7]);
    }

    half2 hh[4];
#pragma unroll
    for (int q = 0; q < 4; q++)
        hh[q] = __halves2half2(__float2half_rn(acc[2 * q]),
                               __float2half_rn(acc[2 * q + 1]));
    uint4 pH = make_uint4(h2_as_u32(hh[0]), h2_as_u32(hh[1]),
                          h2_as_u32(hh[2]), h2_as_u32(hh[3]));
    *(uint4*)(out + (size_t)node * C + lane * 8) = pH;
}

// ---------------- tensor-core GEMM (fp16 A, split-fp16 W) -------------------
// out[M,256] = A @ W^T + epilogue.  BM=128, BN=64, BK=32, 256 threads =
// 8 warps (4m x 2n), warp tile 32x32 = 2 m-atoms x 4 n-atoms, m16n8k16.
// 2 terms: A*Wh + A*Wl  (weight residual kept; A is fp16-rounded aggregate).
template <int K, bool BN_RELU, bool OUT_HALF>
__global__ void gemm_tc_kernel(const __half* __restrict__ A,
                               const __half* __restrict__ Bh,
                               const __half* __restrict__ Bl,
                               const float* __restrict__ bias,
                               const float* __restrict__ gam,
                               const float* __restrict__ bet,
                               const float* __restrict__ mu,
                               const float* __restrict__ var,
                               void* __restrict__ out_v) {
    constexpr int BM = 128, BN = 64, BK = 32;
    constexpr int PK = 20;  // row pitch in half2: conflict-free frag LDS
    __shared__ __align__(16) half2 sA[BM][PK];
    __shared__ __align__(16) half2 sBh[BN][PK];
    __shared__ __align__(16) half2 sBl[BN][PK];

    int m0 = blockIdx.x * BM;
    int n0 = blockIdx.y * BN;
    int tid = threadIdx.x;
    int lane = tid & 31;
    int g = lane >> 2;        // 0..7
    int t = lane & 3;         // 0..3
    int wid = tid >> 5;       // 0..7
    int wm = wid & 3;         // warp m index (0..3)
    int wn = wid >> 2;        // warp n index (0..1)

    int arow = tid >> 1;            // 0..127
    int akq  = (tid & 1) * 16;      // 0 or 16
    int brow = tid >> 2;            // 0..63
    int bkq  = (tid & 3) * 8;       // 0,8,16,24

    float acc[2][4][4];
#pragma unroll
    for (int i = 0; i < 2; i++)
#pragma unroll
        for (int j = 0; j < 4; j++)
#pragma unroll
            for (int c = 0; c < 4; c++) acc[i][j][c] = 0.f;

    for (int kt = 0; kt < K; kt += BK) {
        {
            int row = m0 + arow;
            uint4 h0 = make_uint4(0, 0, 0, 0), h1 = h0;
            if (row < N_NODES) {
                const __half* ap = A + (size_t)row * K + kt + akq;
                h0 = *(const uint4*)(ap);
                h1 = *(const uint4*)(ap + 8);
            }
            *(uint4*)&sA[arow][akq / 2]     = h0;
            *(uint4*)&sA[arow][akq / 2 + 4] = h1;
        }
        {
            const __half* bp = Bh + (size_t)(n0 + brow) * K + kt + bkq;
            const __half* lp = Bl + (size_t)(n0 + brow) * K + kt + bkq;
            *(uint4*)&sBh[brow][bkq / 2] = *(const uint4*)bp;
            *(uint4*)&sBl[brow][bkq / 2] = *(const uint4*)lp;
        }
        __syncthreads();

#pragma unroll
        for (int ko = 0; ko < 2; ko++) {   // two k16 steps per BK=32 tile
            int kb = ko * 8;               // half2 offset
            unsigned ah[2][4], bh[4][2], bl[4][2];
#pragma unroll
            for (int i = 0; i < 2; i++) {
                int rm = wm * 32 + i * 16;
                ah[i][0] = h2_as_u32(sA[rm + g][kb + t]);
                ah[i][1] = h2_as_u32(sA[rm + g + 8][kb + t]);
                ah[i][2] = h2_as_u32(sA[rm + g][kb + t + 4]);
                ah[i][3] = h2_as_u32(sA[rm + g + 8][kb + t + 4]);
            }
#pragma unroll
            for (int j = 0; j < 4; j++) {
                int cn = wn * 32 + j * 8;
                bh[j][0] = h2_as_u32(sBh[cn + g][kb + t]);
                bh[j][1] = h2_as_u32(sBh[cn + g][kb + t + 4]);
                bl[j][0] = h2_as_u32(sBl[cn + g][kb + t]);
                bl[j][1] = h2_as_u32(sBl[cn + g][kb + t + 4]);
            }
#pragma unroll
            for (int i = 0; i < 2; i++)
#pragma unroll
                for (int j = 0; j < 4; j++) {
                    mma_f16(acc[i][j], ah[i], bh[j]);
                    mma_f16(acc[i][j], ah[i], bl[j]);
                }
        }
        __syncthreads();
    }

    // ---- epilogue: +bias, optional BN(eval)+ReLU ----
#pragma unroll
    for (int j = 0; j < 4; j++) {
        int n = n0 + wn * 32 + j * 8 + 2 * t;
        float b0 = bias[n], b1 = bias[n + 1];
        float s0 = 0.f, s1 = 0.f, t0 = 0.f, t1 = 0.f;
        if (BN_RELU) {
            s0 = gam[n] * rsqrtf(var[n] + 1e-5f);
            t0 = bet[n] - mu[n] * s0;
            s1 = gam[n + 1] * rsqrtf(var[n + 1] + 1e-5f);
            t1 = bet[n + 1] - mu[n + 1] * s1;
        }
#pragma unroll
        for (int i = 0; i < 2; i++) {
            int r0 = m0 + wm * 32 + i * 16 + g;
            int r1 = r0 + 8;
            float z0 = acc[i][j][0] + b0;
            float z1 = acc[i][j][1] + b1;
            float z2 = acc[i][j][2] + b0;
            float z3 = acc[i][j][3] + b1;
            if (BN_RELU) {
                z0 = fmaxf(fmaf(z0, s0, t0), 0.f);
                z1 = fmaxf(fmaf(z1, s1, t1), 0.f);
                z2 = fmaxf(fmaf(z2, s0, t0), 0.f);
                z3 = fmaxf(fmaf(z3, s1, t1), 0.f);
            }
            if (OUT_HALF) {
                __half* oh = (__half*)out_v;
                half2 p0 = __halves2half2(__float2half_rn(z0), __float2half_rn(z1));
                half2 p1 = __halves2half2(__float2half_rn(z2), __float2half_rn(z3));
                if (r0 < N_NODES)
                    *(half2*)(oh + (size_t)r0 * C_OUT + n) = p0;
                if (r1 < N_NODES)
                    *(half2*)(oh + (size_t)r1 * C_OUT + n) = p1;
            } else {
                float* of = (float*)out_v;
                if (r0 < N_NODES)
                    *(float2*)(of + (size_t)r0 * C_OUT + n) = make_float2(z0, z1);
                if (r1 < N_NODES)
                    *(float2*)(of + (size_t)r1 * C_OUT + n) = make_float2(z2, z3);
            }
        }
    }
}

// ---------------- launch ----------------------------------------------------
extern "C" void kernel_launch(void* const* d_in, const int* in_sizes, int n_in,
                              void* d_out, int out_size) {
    const float* x   = (const float*)d_in[0];
    const int*   ei  = (const int*)d_in[1];
    const float* ea  = (const float*)d_in[2];
    const float* W1  = (const float*)d_in[3];
    const float* b1  = (const float*)d_in[4];
    const float* g1  = (const float*)d_in[5];
    const float* be1 = (const float*)d_in[6];
    const float* m1  = (const float*)d_in[7];
    const float* v1  = (const float*)d_in[8];
    const float* W2  = (const float*)d_in[9];
    const float* b2  = (const float*)d_in[10];
    const float* g2  = (const float*)d_in[11];
    const float* be2 = (const float*)d_in[12];
    const float* m2  = (const float*)d_in[13];
    const float* v2  = (const float*)d_in[14];
    const float* W3  = (const float*)d_in[15];
    const float* b3  = (const float*)d_in[16];

    void *p_agg, *p_hf, *p_xh, *p_deg, *p_WH, *p_WL;
    cudaGetSymbolAddress(&p_agg, g_agg);
    cudaGetSymbolAddress(&p_hf, g_hf);
    cudaGetSymbolAddress(&p_xh, g_xh);
    cudaGetSymbolAddress(&p_deg, g_deg);
    cudaGetSymbolAddress(&p_WH, g_WH);
    cudaGetSymbolAddress(&p_WL, g_WL);
    __half* agg = (__half*)p_agg;
    __half* hf  = (__half*)p_hf;
    __half* xh  = (__half*)p_xh;
    __half* WH  = (__half*)p_WH;
    __half* WL  = (__half*)p_WL;
    const int offW2 = W1_N;
    const int offW3 = W1_N + W2_N;

    // ---- CSR build + weight/x conversion (once) ----
    detect_kernel<<<1, 64>>>(ei);
    cudaMemsetAsync(p_deg, 0, N_NODES * sizeof(int));
    split_w_kernel<<<(W_TOTAL + 255) / 256, 256>>>(W1, W2, W3);
    x2h_kernel<<<(N_NODES * 128 / 4 + 255) / 256, 256>>>(x);
    hist_kernel<<<(N_EDGES + 255) / 256, 256>>>(ei);
    scan_p1_kernel<<<SCAN_BLOCKS, 256>>>();
    scan_p2_kernel<<<1, 256>>>();
    scan_p3_kernel<<<SCAN_BLOCKS, 256>>>();
    fill_kernel<<<(N_EDGES + 255) / 256, 256>>>(ei, ea);

    dim3 ggrid((N_NODES + 127) / 128, 4);  // 391 x 4, BM=128 BN=64

    // ---- layer 1: gather x_fp16 (C=128), GEMM K=128 + BN1 + ReLU -> fp16 h --
    gather_kernel<128, true><<<(N_NODES + 15) / 16, 256>>>(xh, agg);
    gemm_tc_kernel<128, true, true><<<ggrid, 256>>>(agg, WH, WL,
                                                    b1, g1, be1, m1, v1, hf);

    // ---- layer 2: gather h_fp16 (C=256), GEMM K=256 + BN2 + ReLU -> fp16 h --
    gather_kernel<256, true><<<(N_NODES + 7) / 8, 256>>>(hf, agg);
    gemm_tc_kernel<256, true, true><<<ggrid, 256>>>(agg, WH + offW2, WL + offW2,
                                                    b2, g2, be2, m2, v2, hf);

    // ---- layer 3: gather h_fp16 (C=256, no weight), GEMM + bias -> fp32 out -
    gather_kernel<256, false><<<(N_NODES + 7) / 8, 256>>>(hf, agg);
    gemm_tc_kernel<256, false, false><<<ggrid, 256>>>(agg, WH + offW3, WL + offW3,
                                                      b3, nullptr, nullptr,
                                                      nullptr, nullptr, d_out);
}

// round 11
// speedup vs baseline: 2.3245x; 1.1191x over previous
#include <cuda_runtime.h>
#include <cuda_fp16.h>

#define N_NODES 50000
#define N_EDGES 1600000
#define C_OUT   256
#define SCAN_BLOCKS 196   // ceil(50000/256)
#define W1_N (256*128)
#define W2_N (256*256)
#define W_TOTAL (W1_N + 2*W2_N)

// ---------------- scratch (static device globals; allocation-free) ----------
__device__ int    g_is64;
__device__ int2   g_edge[N_EDGES];     // (src, __float_as_int(ew)) CSR-sorted
__device__ int    g_deg[N_NODES];
__device__ int    g_blkoff[SCAN_BLOCKS];
__device__ int    g_rowoff[N_NODES + 1];
__device__ int    g_cursor[N_NODES];
__device__ __half g_xh[(size_t)N_NODES * 128];       // fp16 copy of input x
__device__ __half g_hf[(size_t)N_NODES * C_OUT];     // fp16 hidden activations
__device__ __half g_agg[(size_t)N_NODES * C_OUT];    // fp16 aggregate
__device__ __half g_WH[W_TOTAL];

__device__ __forceinline__ unsigned h2_as_u32(half2 v) {
    unsigned u;
    memcpy(&u, &v, 4);
    return u;
}

// d(16x8 f32) += A(16x16 f16) * B(16x8 f16)
__device__ __forceinline__ void mma_f16(float c[4], const unsigned a[4],
                                        const unsigned b[2]) {
    asm("mma.sync.aligned.m16n8k16.row.col.f32.f16.f16.f32 "
        "{%0,%1,%2,%3}, {%4,%5,%6,%7}, {%8,%9}, {%0,%1,%2,%3};"
        : "+f"(c[0]), "+f"(c[1]), "+f"(c[2]), "+f"(c[3])
        : "r"(a[0]), "r"(a[1]), "r"(a[2]), "r"(a[3]), "r"(b[0]), "r"(b[1]));
}

// split weights to fp16 + (block 0) int64-vs-int32 edge_index detection
__global__ void split_w_kernel(const float* __restrict__ W1,
                               const float* __restrict__ W2,
                               const float* __restrict__ W3,
                               const int* __restrict__ ei_words) {
    if (blockIdx.x == 0 && threadIdx.x < 64) {
        __shared__ int nz;
        if (threadIdx.x == 0) nz = 0;
        __syncwarp();
        if (ei_words[2 * threadIdx.x + 1] != 0) atomicOr(&nz, 1);
        __syncwarp();
        if (threadIdx.x == 0) g_is64 = (nz == 0) ? 1 : 0;
    }
    int i = blockIdx.x * blockDim.x + threadIdx.x;
    if (i >= W_TOTAL) return;
    float v;
    if (i < W1_N)               v = W1[i];
    else if (i < W1_N + W2_N)   v = W2[i - W1_N];
    else                        v = W3[i - W1_N - W2_N];
    g_WH[i] = __float2half_rn(v);
}

// convert input x to fp16 (once per launch)
__global__ void x2h_kernel(const float* __restrict__ x) {
    int i = blockIdx.x * blockDim.x + threadIdx.x;
    if (i >= N_NODES * 128 / 4) return;
    float4 v = ((const float4*)x)[i];
    half2 a = __halves2half2(__float2half_rn(v.x), __float2half_rn(v.y));
    half2 b = __halves2half2(__float2half_rn(v.z), __float2half_rn(v.w));
    ((uint2*)g_xh)[i] = make_uint2(h2_as_u32(a), h2_as_u32(b));
}

// histogram dst degrees straight from edge_index (4 edges per thread)
__global__ void hist_kernel(const int* __restrict__ ei) {
    int e0 = (blockIdx.x * blockDim.x + threadIdx.x) * 4;
    if (e0 >= N_EDGES) return;
    if (g_is64) {
        const int2* dw = (const int2*)(ei + 2 * (size_t)N_EDGES);
#pragma unroll
        for (int u = 0; u < 4; u++)
            atomicAdd(&g_deg[dw[e0 + u].x], 1);
    } else {
#pragma unroll
        for (int u = 0; u < 4; u++)
            atomicAdd(&g_deg[ei[N_EDGES + e0 + u]], 1);
    }
}

// ---------------- decoupled 3-phase exclusive scan ---------------------------
__global__ void scan_p1_kernel() {
    int i = blockIdx.x * 256 + threadIdx.x;
    int v = (i < N_NODES) ? g_deg[i] : 0;
#pragma unroll
    for (int o = 16; o > 0; o >>= 1) v += __shfl_down_sync(~0u, v, o);
    __shared__ int ws[8];
    int lane = threadIdx.x & 31, wid = threadIdx.x >> 5;
    if (lane == 0) ws[wid] = v;
    __syncthreads();
    if (threadIdx.x == 0) {
        int s = 0;
#pragma unroll
        for (int w = 0; w < 8; w++) s += ws[w];
        g_blkoff[blockIdx.x] = s;
    }
}

__global__ void scan_p2_kernel() {
    int tid = threadIdx.x;  // 256 threads
    int v = (tid < SCAN_BLOCKS) ? g_blkoff[tid] : 0;
    int lane = tid & 31, wid = tid >> 5;
    int x = v;
#pragma unroll
    for (int o = 1; o < 32; o <<= 1) {
        int t = __shfl_up_sync(~0u, x, o);
        if (lane >= o) x += t;
    }
    __shared__ int ws[8];
    if (lane == 31) ws[wid] = x;
    __syncthreads();
    if (wid == 0 && lane < 8) {
        int w = ws[lane];
#pragma unroll
        for (int o = 1; o < 8; o <<= 1) {
            int t = __shfl_up_sync(0xffu, w, o);
            if (lane >= o) w += t;
        }
        ws[lane] = w;
    }
    __syncthreads();
    int excl = (x - v) + (wid > 0 ? ws[wid - 1] : 0);
    if (tid < SCAN_BLOCKS) g_blkoff[tid] = excl;
    if (tid == 0) g_rowoff[N_NODES] = N_EDGES;
}

__global__ void scan_p3_kernel() {
    int i = blockIdx.x * 256 + threadIdx.x;
    int v = (i < N_NODES) ? g_deg[i] : 0;
    int lane = threadIdx.x & 31, wid = threadIdx.x >> 5;
    int x = v;
#pragma unroll
    for (int o = 1; o < 32; o <<= 1) {
        int t = __shfl_up_sync(~0u, x, o);
        if (lane >= o) x += t;
    }
    __shared__ int ws[8];
    if (lane == 31) ws[wid] = x;
    __syncthreads();
    if (wid == 0 && lane < 8) {
        int w = ws[lane];
#pragma unroll
        for (int o = 1; o < 8; o <<= 1) {
            int t = __shfl_up_sync(0xffu, w, o);
            if (lane >= o) w += t;
        }
        ws[lane] = w;
    }
    __syncthreads();
    int excl = (x - v) + (wid > 0 ? ws[wid - 1] : 0) + g_blkoff[blockIdx.x];
    if (i < N_NODES) {
        g_rowoff[i] = excl;
        g_cursor[i] = excl;
    }
}

// decode edge, compute ew = mean(edge_attr,-1), scatter packed into CSR
__global__ void fill_kernel(const int* __restrict__ ei,
                            const float* __restrict__ ea) {
    int e = blockIdx.x * blockDim.x + threadIdx.x;
    if (e >= N_EDGES) return;
    int s, d;
    if (g_is64) {
        s = ei[2 * (size_t)e];
        d = ei[2 * (size_t)N_EDGES + 2 * (size_t)e];
    } else {
        s = ei[e];
        d = ei[N_EDGES + e];
    }
    const float4* a4 = (const float4*)(ea + (size_t)e * 8);
    float4 u = a4[0];
    float4 v = a4[1];
    float ew = (u.x + u.y + u.z + u.w + v.x + v.y + v.z + v.w) * 0.125f;
    int p = atomicAdd(&g_cursor[d], 1);
    g_edge[p] = make_int2(s, __float_as_int(ew));
}

// ---------------- gather-aggregate (fp16 rows -> fp16 aggregate) ------------
// out_i = sum_{e: dst=i} in[src_e] * w_e ; fp32 accum, fp16 store.
// Each lane owns 8 channels: one uint4 (16B) per gathered row.
template <int C, bool USE_W>
__global__ void gather_kernel(const __half* __restrict__ in,
                              __half* __restrict__ out) {
    constexpr int L = C / 8;        // lanes per node (16 or 32)
    constexpr int G = 256 / L;      // nodes per 256-thread block
    int grp  = threadIdx.x / L;
    int lane = threadIdx.x % L;
    int node = blockIdx.x * G + grp;
    if (node >= N_NODES) return;

    int e0 = g_rowoff[node];
    int e1 = g_rowoff[node + 1];
    const uint4* in4 = (const uint4*)in;   // row stride = C/8 uint4
    float acc[8];
#pragma unroll
    for (int q = 0; q < 8; q++) acc[q] = 0.f;

    int e = e0;
    for (; e + 4 <= e1; e += 4) {
        int2 p[4];
#pragma unroll
        for (int u = 0; u < 4; u++) p[u] = g_edge[e + u];
#pragma unroll
        for (int u = 0; u < 4; u++) {
            float w = USE_W ? __int_as_float(p[u].y) : 1.0f;
            uint4 r = in4[(size_t)p[u].x * L + lane];
            half2 h0 = *(half2*)&r.x, h1 = *(half2*)&r.y;
            half2 h2 = *(half2*)&r.z, h3 = *(half2*)&r.w;
            float2 f0 = __half22float2(h0), f1 = __half22float2(h1);
            float2 f2 = __half22float2(h2), f3 = __half22float2(h3);
            acc[0] = fmaf(f0.x, w, acc[0]); acc[1] = fmaf(f0.y, w, acc[1]);
            acc[2] = fmaf(f1.x, w, acc[2]); acc[3] = fmaf(f1.y, w, acc[3]);
            acc[4] = fmaf(f2.x, w, acc[4]); acc[5] = fmaf(f2.y, w, acc[5]);
            acc[6] = fmaf(f3.x, w, acc[6]); acc[7] = fmaf(f3.y, w, acc[7]);
        }
    }
    for (; e < e1; e++) {
        int2 p = g_edge[e];
        float w = USE_W ? __int_as_float(p.y) : 1.0f;
        uint4 r = in4[(size_t)p.x * L + lane];
        half2 h0 = *(half2*)&r.x, h1 = *(half2*)&r.y;
        half2 h2 = *(half2*)&r.z, h3 = *(half2*)&r.w;
        float2 f0 = __half22float2(h0), f1 = __half22float2(h1);
        float2 f2 = __half22float2(h2), f3 = __half22float2(h3);
        acc[0] = fmaf(f0.x, w, acc[0]); acc[1] = fmaf(f0.y, w, acc[1]);
        acc[2] = fmaf(f1.x, w, acc[2]); acc[3] = fmaf(f1.y, w, acc[3]);
        acc[4] = fmaf(f2.x, w, acc[4]); acc[5] = fmaf(f2.y, w, acc[5]);
        acc[6] = fmaf(f3.x, w, acc[6]); acc[7] = fmaf(f3.y, w, acc[7]);
    }

    half2 hh[4];
#pragma unroll
    for (int q = 0; q < 4; q++)
        hh[q] = __halves2half2(__float2half_rn(acc[2 * q]),
                               __float2half_rn(acc[2 * q + 1]));
    uint4 pH = make_uint4(h2_as_u32(hh[0]), h2_as_u32(hh[1]),
                          h2_as_u32(hh[2]), h2_as_u32(hh[3]));
    *(uint4*)(out + (size_t)node * C + lane * 8) = pH;
}

// ---------------- tensor-core GEMM (fp16 x fp16, fp32 accum) ----------------
// out[M,256] = A @ W^T + epilogue.  BM=128, BN=64, BK=32, 256 threads =
// 8 warps (4m x 2n), warp tile 32x32 = 2 m-atoms x 4 n-atoms, m16n8k16.
template <int K, bool BN_RELU, bool OUT_HALF>
__global__ void gemm_tc_kernel(const __half* __restrict__ A,
                               const __half* __restrict__ B,
                               const float* __restrict__ bias,
                               const float* __restrict__ gam,
                               const float* __restrict__ bet,
                               const float* __restrict__ mu,
                               const float* __restrict__ var,
                               void* __restrict__ out_v) {
    constexpr int BM = 128, BN = 64, BK = 32;
    constexpr int PK = 20;  // row pitch in half2: conflict-free frag LDS
    __shared__ __align__(16) half2 sA[BM][PK];
    __shared__ __align__(16) half2 sB[BN][PK];

    int m0 = blockIdx.x * BM;
    int n0 = blockIdx.y * BN;
    int tid = threadIdx.x;
    int lane = tid & 31;
    int g = lane >> 2;        // 0..7
    int t = lane & 3;         // 0..3
    int wid = tid >> 5;       // 0..7
    int wm = wid & 3;         // warp m index (0..3)
    int wn = wid >> 2;        // warp n index (0..1)

    int arow = tid >> 1;            // 0..127
    int akq  = (tid & 1) * 16;      // 0 or 16
    int brow = tid >> 2;            // 0..63
    int bkq  = (tid & 3) * 8;       // 0,8,16,24

    float acc[2][4][4];
#pragma unroll
    for (int i = 0; i < 2; i++)
#pragma unroll
        for (int j = 0; j < 4; j++)
#pragma unroll
            for (int c = 0; c < 4; c++) acc[i][j][c] = 0.f;

    for (int kt = 0; kt < K; kt += BK) {
        {
            int row = m0 + arow;
            uint4 h0 = make_uint4(0, 0, 0, 0), h1 = h0;
            if (row < N_NODES) {
                const __half* ap = A + (size_t)row * K + kt + akq;
                h0 = *(const uint4*)(ap);
                h1 = *(const uint4*)(ap + 8);
            }
            *(uint4*)&sA[arow][akq / 2]     = h0;
            *(uint4*)&sA[arow][akq / 2 + 4] = h1;
        }
        {
            const __half* bp = B + (size_t)(n0 + brow) * K + kt + bkq;
            *(uint4*)&sB[brow][bkq / 2] = *(const uint4*)bp;
        }
        __syncthreads();

#pragma unroll
        for (int ko = 0; ko < 2; ko++) {   // two k16 steps per BK=32 tile
            int kb = ko * 8;               // half2 offset
            unsigned ah[2][4], bh[4][2];
#pragma unroll
            for (int i = 0; i < 2; i++) {
                int rm = wm * 32 + i * 16;
                ah[i][0] = h2_as_u32(sA[rm + g][kb + t]);
                ah[i][1] = h2_as_u32(sA[rm + g + 8][kb + t]);
                ah[i][2] = h2_as_u32(sA[rm + g][kb + t + 4]);
                ah[i][3] = h2_as_u32(sA[rm + g + 8][kb + t + 4]);
            }
#pragma unroll
            for (int j = 0; j < 4; j++) {
                int cn = wn * 32 + j * 8;
                bh[j][0] = h2_as_u32(sB[cn + g][kb + t]);
                bh[j][1] = h2_as_u32(sB[cn + g][kb + t + 4]);
            }
#pragma unroll
            for (int i = 0; i < 2; i++)
#pragma unroll
                for (int j = 0; j < 4; j++)
                    mma_f16(acc[i][j], ah[i], bh[j]);
        }
        __syncthreads();
    }

    // ---- epilogue: +bias, optional BN(eval)+ReLU ----
#pragma unroll
    for (int j = 0; j < 4; j++) {
        int n = n0 + wn * 32 + j * 8 + 2 * t;
        float b0 = bias[n], b1 = bias[n + 1];
        float s0 = 0.f, s1 = 0.f, t0 = 0.f, t1 = 0.f;
        if (BN_RELU) {
            s0 = gam[n] * rsqrtf(var[n] + 1e-5f);
            t0 = bet[n] - mu[n] * s0;
            s1 = gam[n + 1] * rsqrtf(var[n + 1] + 1e-5f);
            t1 = bet[n + 1] - mu[n + 1] * s1;
        }
#pragma unroll
        for (int i = 0; i < 2; i++) {
            int r0 = m0 + wm * 32 + i * 16 + g;
            int r1 = r0 + 8;
            float z0 = acc[i][j][0] + b0;
            float z1 = acc[i][j][1] + b1;
            float z2 = acc[i][j][2] + b0;
            float z3 = acc[i][j][3] + b1;
            if (BN_RELU) {
                z0 = fmaxf(fmaf(z0, s0, t0), 0.f);
                z1 = fmaxf(fmaf(z1, s1, t1), 0.f);
                z2 = fmaxf(fmaf(z2, s0, t0), 0.f);
                z3 = fmaxf(fmaf(z3, s1, t1), 0.f);
            }
            if (OUT_HALF) {
                __half* oh = (__half*)out_v;
                half2 p0 = __halves2half2(__float2half_rn(z0), __float2half_rn(z1));
                half2 p1 = __halves2half2(__float2half_rn(z2), __float2half_rn(z3));
                if (r0 < N_NODES)
                    *(half2*)(oh + (size_t)r0 * C_OUT + n) = p0;
                if (r1 < N_NODES)
                    *(half2*)(oh + (size_t)r1 * C_OUT + n) = p1;
            } else {
                float* of = (float*)out_v;
                if (r0 < N_NODES)
                    *(float2*)(of + (size_t)r0 * C_OUT + n) = make_float2(z0, z1);
                if (r1 < N_NODES)
                    *(float2*)(of + (size_t)r1 * C_OUT + n) = make_float2(z2, z3);
            }
        }
    }
}

// ---------------- launch ----------------------------------------------------
extern "C" void kernel_launch(void* const* d_in, const int* in_sizes, int n_in,
                              void* d_out, int out_size) {
    const float* x   = (const float*)d_in[0];
    const int*   ei  = (const int*)d_in[1];
    const float* ea  = (const float*)d_in[2];
    const float* W1  = (const float*)d_in[3];
    const float* b1  = (const float*)d_in[4];
    const float* g1  = (const float*)d_in[5];
    const float* be1 = (const float*)d_in[6];
    const float* m1  = (const float*)d_in[7];
    const float* v1  = (const float*)d_in[8];
    const float* W2  = (const float*)d_in[9];
    const float* b2  = (const float*)d_in[10];
    const float* g2  = (const float*)d_in[11];
    const float* be2 = (const float*)d_in[12];
    const float* m2  = (const float*)d_in[13];
    const float* v2  = (const float*)d_in[14];
    const float* W3  = (const float*)d_in[15];
    const float* b3  = (const float*)d_in[16];

    void *p_agg, *p_hf, *p_xh, *p_deg, *p_WH;
    cudaGetSymbolAddress(&p_agg, g_agg);
    cudaGetSymbolAddress(&p_hf, g_hf);
    cudaGetSymbolAddress(&p_xh, g_xh);
    cudaGetSymbolAddress(&p_deg, g_deg);
    cudaGetSymbolAddress(&p_WH, g_WH);
    __half* agg = (__half*)p_agg;
    __half* hf  = (__half*)p_hf;
    __half* xh  = (__half*)p_xh;
    __half* WH  = (__half*)p_WH;
    const int offW2 = W1_N;
    const int offW3 = W1_N + W2_N;

    // ---- CSR build + weight/x conversion (once) ----
    cudaMemsetAsync(p_deg, 0, N_NODES * sizeof(int));
    split_w_kernel<<<(W_TOTAL + 255) / 256, 256>>>(W1, W2, W3, ei);
    x2h_kernel<<<(N_NODES * 128 / 4 + 255) / 256, 256>>>(x);
    hist_kernel<<<(N_EDGES / 4 + 255) / 256, 256>>>(ei);
    scan_p1_kernel<<<SCAN_BLOCKS, 256>>>();
    scan_p2_kernel<<<1, 256>>>();
    scan_p3_kernel<<<SCAN_BLOCKS, 256>>>();
    fill_kernel<<<(N_EDGES + 255) / 256, 256>>>(ei, ea);

    dim3 ggrid((N_NODES + 127) / 128, 4);  // 391 x 4, BM=128 BN=64

    // ---- layer 1: gather x_fp16 (C=128), GEMM K=128 + BN1 + ReLU -> fp16 h --
    gather_kernel<128, true><<<(N_NODES + 15) / 16, 256>>>(xh, agg);
    gemm_tc_kernel<128, true, true><<<ggrid, 256>>>(agg, WH,
                                                    b1, g1, be1, m1, v1, hf);

    // ---- layer 2: gather h_fp16 (C=256), GEMM K=256 + BN2 + ReLU -> fp16 h --
    gather_kernel<256, true><<<(N_NODES + 7) / 8, 256>>>(hf, agg);
    gemm_tc_kernel<256, true, true><<<ggrid, 256>>>(agg, WH + offW2,
                                                    b2, g2, be2, m2, v2, hf);

    // ---- layer 3: gather h_fp16 (C=256, no weight), GEMM + bias -> fp32 out -
    gather_kernel<256, false><<<(N_NODES + 7) / 8, 256>>>(hf, agg);
    gemm_tc_kernel<256, false, false><<<ggrid, 256>>>(agg, WH + offW3,
                                                      b3, nullptr, nullptr,
                                                      nullptr, nullptr, d_out);
}

// round 12
// speedup vs baseline: 2.3440x; 1.0084x over previous
#include <cuda_runtime.h>
#include <cuda_fp16.h>

#define N_NODES 50000
#define N_EDGES 1600000
#define C_OUT   256
#define SCAN_BLOCKS 196   // ceil(50000/256)
#define W1_N (256*128)
#define W2_N (256*256)
#define W_TOTAL (W1_N + 2*W2_N)

// ---------------- scratch (static device globals; allocation-free) ----------
__device__ int    g_is64;
__device__ int2   g_edge[N_EDGES];     // (src, __float_as_int(ew)) CSR-sorted
__device__ int    g_deg[N_NODES];
__device__ int    g_blkoff[SCAN_BLOCKS];
__device__ int    g_rowoff[N_NODES + 1];
__device__ int    g_cursor[N_NODES];
__device__ __half g_xh[(size_t)N_NODES * 128];       // fp16 copy of input x
__device__ __half g_hf[(size_t)N_NODES * C_OUT];     // fp16 hidden activations
__device__ __half g_agg[(size_t)N_NODES * C_OUT];    // fp16 aggregate
__device__ __half g_WH[W_TOTAL];

__device__ __forceinline__ unsigned h2_as_u32(half2 v) {
    unsigned u;
    memcpy(&u, &v, 4);
    return u;
}

// d(16x8 f32) += A(16x16 f16) * B(16x8 f16)
__device__ __forceinline__ void mma_f16(float c[4], const unsigned a[4],
                                        const unsigned b[2]) {
    asm("mma.sync.aligned.m16n8k16.row.col.f32.f16.f16.f32 "
        "{%0,%1,%2,%3}, {%4,%5,%6,%7}, {%8,%9}, {%0,%1,%2,%3};"
        : "+f"(c[0]), "+f"(c[1]), "+f"(c[2]), "+f"(c[3])
        : "r"(a[0]), "r"(a[1]), "r"(a[2]), "r"(a[3]), "r"(b[0]), "r"(b[1]));
}

// split weights to fp16 + (block 0) int64-vs-int32 edge_index detection
__global__ void split_w_kernel(const float* __restrict__ W1,
                               const float* __restrict__ W2,
                               const float* __restrict__ W3,
                               const int* __restrict__ ei_words) {
    if (blockIdx.x == 0 && threadIdx.x < 64) {
        __shared__ int nz;
        if (threadIdx.x == 0) nz = 0;
        __syncwarp();
        if (ei_words[2 * threadIdx.x + 1] != 0) atomicOr(&nz, 1);
        __syncwarp();
        if (threadIdx.x == 0) g_is64 = (nz == 0) ? 1 : 0;
    }
    int i = blockIdx.x * blockDim.x + threadIdx.x;
    if (i >= W_TOTAL) return;
    float v;
    if (i < W1_N)               v = W1[i];
    else if (i < W1_N + W2_N)   v = W2[i - W1_N];
    else                        v = W3[i - W1_N - W2_N];
    g_WH[i] = __float2half_rn(v);
}

// convert input x to fp16 (once per launch)
__global__ void x2h_kernel(const float* __restrict__ x) {
    int i = blockIdx.x * blockDim.x + threadIdx.x;
    if (i >= N_NODES * 128 / 4) return;
    float4 v = ((const float4*)x)[i];
    half2 a = __halves2half2(__float2half_rn(v.x), __float2half_rn(v.y));
    half2 b = __halves2half2(__float2half_rn(v.z), __float2half_rn(v.w));
    ((uint2*)g_xh)[i] = make_uint2(h2_as_u32(a), h2_as_u32(b));
}

// histogram dst degrees straight from edge_index (8 edges/thread, int4 loads)
__global__ void hist_kernel(const int* __restrict__ ei) {
    int e0 = (blockIdx.x * blockDim.x + threadIdx.x) * 8;
    if (e0 >= N_EDGES) return;
    if (g_is64) {
        const int4* dw = (const int4*)(ei + 2 * (size_t)N_EDGES);  // 2 edges per int4
#pragma unroll
        for (int u = 0; u < 4; u++) {
            int4 v = dw[e0 / 2 + u];
            atomicAdd(&g_deg[v.x], 1);
            atomicAdd(&g_deg[v.z], 1);
        }
    } else {
        const int4* dw = (const int4*)(ei + N_EDGES);              // 4 edges per int4
#pragma unroll
        for (int u = 0; u < 2; u++) {
            int4 v = dw[e0 / 4 + u];
            atomicAdd(&g_deg[v.x], 1);
            atomicAdd(&g_deg[v.y], 1);
            atomicAdd(&g_deg[v.z], 1);
            atomicAdd(&g_deg[v.w], 1);
        }
    }
}

// ---------------- decoupled 3-phase exclusive scan ---------------------------
__global__ void scan_p1_kernel() {
    int i = blockIdx.x * 256 + threadIdx.x;
    int v = (i < N_NODES) ? g_deg[i] : 0;
#pragma unroll
    for (int o = 16; o > 0; o >>= 1) v += __shfl_down_sync(~0u, v, o);
    __shared__ int ws[8];
    int lane = threadIdx.x & 31, wid = threadIdx.x >> 5;
    if (lane == 0) ws[wid] = v;
    __syncthreads();
    if (threadIdx.x == 0) {
        int s = 0;
#pragma unroll
        for (int w = 0; w < 8; w++) s += ws[w];
        g_blkoff[blockIdx.x] = s;
    }
}

__global__ void scan_p2_kernel() {
    int tid = threadIdx.x;  // 256 threads
    int v = (tid < SCAN_BLOCKS) ? g_blkoff[tid] : 0;
    int lane = tid & 31, wid = tid >> 5;
    int x = v;
#pragma unroll
    for (int o = 1; o < 32; o <<= 1) {
        int t = __shfl_up_sync(~0u, x, o);
        if (lane >= o) x += t;
    }
    __shared__ int ws[8];
    if (lane == 31) ws[wid] = x;
    __syncthreads();
    if (wid == 0 && lane < 8) {
        int w = ws[lane];
#pragma unroll
        for (int o = 1; o < 8; o <<= 1) {
            int t = __shfl_up_sync(0xffu, w, o);
            if (lane >= o) w += t;
        }
        ws[lane] = w;
    }
    __syncthreads();
    int excl = (x - v) + (wid > 0 ? ws[wid - 1] : 0);
    if (tid < SCAN_BLOCKS) g_blkoff[tid] = excl;
    if (tid == 0) g_rowoff[N_NODES] = N_EDGES;
}

__global__ void scan_p3_kernel() {
    int i = blockIdx.x * 256 + threadIdx.x;
    int v = (i < N_NODES) ? g_deg[i] : 0;
    int lane = threadIdx.x & 31, wid = threadIdx.x >> 5;
    int x = v;
#pragma unroll
    for (int o = 1; o < 32; o <<= 1) {
        int t = __shfl_up_sync(~0u, x, o);
        if (lane >= o) x += t;
    }
    __shared__ int ws[8];
    if (lane == 31) ws[wid] = x;
    __syncthreads();
    if (wid == 0 && lane < 8) {
        int w = ws[lane];
#pragma unroll
        for (int o = 1; o < 8; o <<= 1) {
            int t = __shfl_up_sync(0xffu, w, o);
            if (lane >= o) w += t;
        }
        ws[lane] = w;
    }
    __syncthreads();
    int excl = (x - v) + (wid > 0 ? ws[wid - 1] : 0) + g_blkoff[blockIdx.x];
    if (i < N_NODES) {
        g_rowoff[i] = excl;
        g_cursor[i] = excl;
    }
}

// decode 2 edges/thread, ew = mean(edge_attr,-1), scatter packed into CSR
__global__ void fill_kernel(const int* __restrict__ ei,
                            const float* __restrict__ ea) {
    int e0 = (blockIdx.x * blockDim.x + threadIdx.x) * 2;
    if (e0 >= N_EDGES) return;
    int s0, s1, d0, d1;
    if (g_is64) {
        int4 sv = *(const int4*)(ei + 2 * (size_t)e0);
        int4 dv = *(const int4*)(ei + 2 * (size_t)N_EDGES + 2 * (size_t)e0);
        s0 = sv.x; s1 = sv.z;
        d0 = dv.x; d1 = dv.z;
    } else {
        int2 sv = *(const int2*)(ei + e0);
        int2 dv = *(const int2*)(ei + N_EDGES + e0);
        s0 = sv.x; s1 = sv.y;
        d0 = dv.x; d1 = dv.y;
    }
    const float4* a4 = (const float4*)(ea + (size_t)e0 * 8);
    float4 u0 = a4[0], v0 = a4[1], u1 = a4[2], v1 = a4[3];
    float ew0 = (u0.x + u0.y + u0.z + u0.w + v0.x + v0.y + v0.z + v0.w) * 0.125f;
    float ew1 = (u1.x + u1.y + u1.z + u1.w + v1.x + v1.y + v1.z + v1.w) * 0.125f;
    int p0 = atomicAdd(&g_cursor[d0], 1);
    g_edge[p0] = make_int2(s0, __float_as_int(ew0));
    int p1 = atomicAdd(&g_cursor[d1], 1);
    g_edge[p1] = make_int2(s1, __float_as_int(ew1));
}

// ---------------- gather-aggregate (fp16 rows -> fp16 aggregate) ------------
// out_i = sum_{e: dst=i} in[src_e] * w_e ; fp32 accum, fp16 store.
// Each lane owns 8 channels: one uint4 (16B) per gathered row. 8-way edge
// unroll for MLP (8 outstanding row reads per thread).
template <int C, bool USE_W>
__global__ void gather_kernel(const __half* __restrict__ in,
                              __half* __restrict__ out) {
    constexpr int L = C / 8;        // lanes per node (16 or 32)
    constexpr int G = 256 / L;      // nodes per 256-thread block
    int grp  = threadIdx.x / L;
    int lane = threadIdx.x % L;
    int node = blockIdx.x * G + grp;
    if (node >= N_NODES) return;

    int e0 = g_rowoff[node];
    int e1 = g_rowoff[node + 1];
    const uint4* in4 = (const uint4*)in;   // row stride = C/8 uint4
    float acc[8];
#pragma unroll
    for (int q = 0; q < 8; q++) acc[q] = 0.f;

    int e = e0;
    for (; e + 8 <= e1; e += 8) {
        int2 p[8];
#pragma unroll
        for (int u = 0; u < 8; u++) p[u] = g_edge[e + u];
        uint4 r[8];
#pragma unroll
        for (int u = 0; u < 8; u++) r[u] = in4[(size_t)p[u].x * L + lane];
#pragma unroll
        for (int u = 0; u < 8; u++) {
            float w = USE_W ? __int_as_float(p[u].y) : 1.0f;
            half2 h0 = *(half2*)&r[u].x, h1 = *(half2*)&r[u].y;
            half2 h2 = *(half2*)&r[u].z, h3 = *(half2*)&r[u].w;
            float2 f0 = __half22float2(h0), f1 = __half22float2(h1);
            float2 f2 = __half22float2(h2), f3 = __half22float2(h3);
            acc[0] = fmaf(f0.x, w, acc[0]); acc[1] = fmaf(f0.y, w, acc[1]);
            acc[2] = fmaf(f1.x, w, acc[2]); acc[3] = fmaf(f1.y, w, acc[3]);
            acc[4] = fmaf(f2.x, w, acc[4]); acc[5] = fmaf(f2.y, w, acc[5]);
            acc[6] = fmaf(f3.x, w, acc[6]); acc[7] = fmaf(f3.y, w, acc[7]);
        }
    }
    for (; e < e1; e++) {
        int2 p = g_edge[e];
        float w = USE_W ? __int_as_float(p.y) : 1.0f;
        uint4 r = in4[(size_t)p.x * L + lane];
        half2 h0 = *(half2*)&r.x, h1 = *(half2*)&r.y;
        half2 h2 = *(half2*)&r.z, h3 = *(half2*)&r.w;
        float2 f0 = __half22float2(h0), f1 = __half22float2(h1);
        float2 f2 = __half22float2(h2), f3 = __half22float2(h3);
        acc[0] = fmaf(f0.x, w, acc[0]); acc[1] = fmaf(f0.y, w, acc[1]);
        acc[2] = fmaf(f1.x, w, acc[2]); acc[3] = fmaf(f1.y, w, acc[3]);
        acc[4] = fmaf(f2.x, w, acc[4]); acc[5] = fmaf(f2.y, w, acc[5]);
        acc[6] = fmaf(f3.x, w, acc[6]); acc[7] = fmaf(f3.y, w, acc[7]);
    }

    half2 hh[4];
#pragma unroll
    for (int q = 0; q < 4; q++)
        hh[q] = __halves2half2(__float2half_rn(acc[2 * q]),
                               __float2half_rn(acc[2 * q + 1]));
    uint4 pH = make_uint4(h2_as_u32(hh[0]), h2_as_u32(hh[1]),
                          h2_as_u32(hh[2]), h2_as_u32(hh[3]));
    *(uint4*)(out + (size_t)node * C + lane * 8) = pH;
}

// ---------------- tensor-core GEMM (fp16 x fp16, fp32 accum) ----------------
// out[M,256] = A @ W^T + epilogue.  BM=128, BN=64, BK=32, 256 threads =
// 8 warps (4m x 2n), warp tile 32x32 = 2 m-atoms x 4 n-atoms, m16n8k16.
template <int K, bool BN_RELU, bool OUT_HALF>
__global__ void gemm_tc_kernel(const __half* __restrict__ A,
                               const __half* __restrict__ B,
                               const float* __restrict__ bias,
                               const float* __restrict__ gam,
                               const float* __restrict__ bet,
                               const float* __restrict__ mu,
                               const float* __restrict__ var,
                               void* __restrict__ out_v) {
    constexpr int BM = 128, BN = 64, BK = 32;
    constexpr int PK = 20;  // row pitch in half2: conflict-free frag LDS
    __shared__ __align__(16) half2 sA[BM][PK];
    __shared__ __align__(16) half2 sB[BN][PK];

    int m0 = blockIdx.x * BM;
    int n0 = blockIdx.y * BN;
    int tid = threadIdx.x;
    int lane = tid & 31;
    int g = lane >> 2;        // 0..7
    int t = lane & 3;         // 0..3
    int wid = tid >> 5;       // 0..7
    int wm = wid & 3;         // warp m index (0..3)
    int wn = wid >> 2;        // warp n index (0..1)

    int arow = tid >> 1;            // 0..127
    int akq  = (tid & 1) * 16;      // 0 or 16
    int brow = tid >> 2;            // 0..63
    int bkq  = (tid & 3) * 8;       // 0,8,16,24

    float acc[2][4][4];
#pragma unroll
    for (int i = 0; i < 2; i++)
#pragma unroll
        for (int j = 0; j < 4; j++)
#pragma unroll
            for (int c = 0; c < 4; c++) acc[i][j][c] = 0.f;

    for (int kt = 0; kt < K; kt += BK) {
        {
            int row = m0 + arow;
            uint4 h0 = make_uint4(0, 0, 0, 0), h1 = h0;
            if (row < N_NODES) {
                const __half* ap = A + (size_t)row * K + kt + akq;
                h0 = *(const uint4*)(ap);
                h1 = *(const uint4*)(ap + 8);
            }
            *(uint4*)&sA[arow][akq / 2]     = h0;
            *(uint4*)&sA[arow][akq / 2 + 4] = h1;
        }
        {
            const __half* bp = B + (size_t)(n0 + brow) * K + kt + bkq;
            *(uint4*)&sB[brow][bkq / 2] = *(const uint4*)bp;
        }
        __syncthreads();

#pragma unroll
        for (int ko = 0; ko < 2; ko++) {   // two k16 steps per BK=32 tile
            int kb = ko * 8;               // half2 offset
            unsigned ah[2][4], bh[4][2];
#pragma unroll
            for (int i = 0; i < 2; i++) {
                int rm = wm * 32 + i * 16;
                ah[i][0] = h2_as_u32(sA[rm + g][kb + t]);
                ah[i][1] = h2_as_u32(sA[rm + g + 8][kb + t]);
                ah[i][2] = h2_as_u32(sA[rm + g][kb + t + 4]);
                ah[i][3] = h2_as_u32(sA[rm + g + 8][kb + t + 4]);
            }
#pragma unroll
            for (int j = 0; j < 4; j++) {
                int cn = wn * 32 + j * 8;
                bh[j][0] = h2_as_u32(sB[cn + g][kb + t]);
                bh[j][1] = h2_as_u32(sB[cn + g][kb + t + 4]);
            }
#pragma unroll
            for (int i = 0; i < 2; i++)
#pragma unroll
                for (int j = 0; j < 4; j++)
                    mma_f16(acc[i][j], ah[i], bh[j]);
        }
        __syncthreads();
    }

    // ---- epilogue: +bias, optional BN(eval)+ReLU ----
#pragma unroll
    for (int j = 0; j < 4; j++) {
        int n = n0 + wn * 32 + j * 8 + 2 * t;
        float b0 = bias[n], b1 = bias[n + 1];
        float s0 = 0.f, s1 = 0.f, t0 = 0.f, t1 = 0.f;
        if (BN_RELU) {
            s0 = gam[n] * rsqrtf(var[n] + 1e-5f);
            t0 = bet[n] - mu[n] * s0;
            s1 = gam[n + 1] * rsqrtf(var[n + 1] + 1e-5f);
            t1 = bet[n + 1] - mu[n + 1] * s1;
        }
#pragma unroll
        for (int i = 0; i < 2; i++) {
            int r0 = m0 + wm * 32 + i * 16 + g;
            int r1 = r0 + 8;
            float z0 = acc[i][j][0] + b0;
            float z1 = acc[i][j][1] + b1;
            float z2 = acc[i][j][2] + b0;
            float z3 = acc[i][j][3] + b1;
            if (BN_RELU) {
                z0 = fmaxf(fmaf(z0, s0, t0), 0.f);
                z1 = fmaxf(fmaf(z1, s1, t1), 0.f);
                z2 = fmaxf(fmaf(z2, s0, t0), 0.f);
                z3 = fmaxf(fmaf(z3, s1, t1), 0.f);
            }
            if (OUT_HALF) {
                __half* oh = (__half*)out_v;
                half2 p0 = __halves2half2(__float2half_rn(z0), __float2half_rn(z1));
                half2 p1 = __halves2half2(__float2half_rn(z2), __float2half_rn(z3));
                if (r0 < N_NODES)
                    *(half2*)(oh + (size_t)r0 * C_OUT + n) = p0;
                if (r1 < N_NODES)
                    *(half2*)(oh + (size_t)r1 * C_OUT + n) = p1;
            } else {
                float* of = (float*)out_v;
                if (r0 < N_NODES)
                    *(float2*)(of + (size_t)r0 * C_OUT + n) = make_float2(z0, z1);
                if (r1 < N_NODES)
                    *(float2*)(of + (size_t)r1 * C_OUT + n) = make_float2(z2, z3);
            }
        }
    }
}

// ---------------- launch ----------------------------------------------------
extern "C" void kernel_launch(void* const* d_in, const int* in_sizes, int n_in,
                              void* d_out, int out_size) {
    const float* x   = (const float*)d_in[0];
    const int*   ei  = (const int*)d_in[1];
    const float* ea  = (const float*)d_in[2];
    const float* W1  = (const float*)d_in[3];
    const float* b1  = (const float*)d_in[4];
    const float* g1  = (const float*)d_in[5];
    const float* be1 = (const float*)d_in[6];
    const float* m1  = (const float*)d_in[7];
    const float* v1  = (const float*)d_in[8];
    const float* W2  = (const float*)d_in[9];
    const float* b2  = (const float*)d_in[10];
    const float* g2  = (const float*)d_in[11];
    const float* be2 = (const float*)d_in[12];
    const float* m2  = (const float*)d_in[13];
    const float* v2  = (const float*)d_in[14];
    const float* W3  = (const float*)d_in[15];
    const float* b3  = (const float*)d_in[16];

    void *p_agg, *p_hf, *p_xh, *p_deg, *p_WH;
    cudaGetSymbolAddress(&p_agg, g_agg);
    cudaGetSymbolAddress(&p_hf, g_hf);
    cudaGetSymbolAddress(&p_xh, g_xh);
    cudaGetSymbolAddress(&p_deg, g_deg);
    cudaGetSymbolAddress(&p_WH, g_WH);
    __half* agg = (__half*)p_agg;
    __half* hf  = (__half*)p_hf;
    __half* xh  = (__half*)p_xh;
    __half* WH  = (__half*)p_WH;
    const int offW2 = W1_N;
    const int offW3 = W1_N + W2_N;

    // ---- CSR build + weight/x conversion (once) ----
    cudaMemsetAsync(p_deg, 0, N_NODES * sizeof(int));
    split_w_kernel<<<(W_TOTAL + 255) / 256, 256>>>(W1, W2, W3, ei);
    x2h_kernel<<<(N_NODES * 128 / 4 + 255) / 256, 256>>>(x);
    hist_kernel<<<(N_EDGES / 8 + 255) / 256, 256>>>(ei);
    scan_p1_kernel<<<SCAN_BLOCKS, 256>>>();
    scan_p2_kernel<<<1, 256>>>();
    scan_p3_kernel<<<SCAN_BLOCKS, 256>>>();
    fill_kernel<<<(N_EDGES / 2 + 255) / 256, 256>>>(ei, ea);

    dim3 ggrid((N_NODES + 127) / 128, 4);  // 391 x 4, BM=128 BN=64

    // ---- layer 1: gather x_fp16 (C=128), GEMM K=128 + BN1 + ReLU -> fp16 h --
    gather_kernel<128, true><<<(N_NODES + 15) / 16, 256>>>(xh, agg);
    gemm_tc_kernel<128, true, true><<<ggrid, 256>>>(agg, WH,
                                                    b1, g1, be1, m1, v1, hf);

    // ---- layer 2: gather h_fp16 (C=256), GEMM K=256 + BN2 + ReLU -> fp16 h --
    gather_kernel<256, true><<<(N_NODES + 7) / 8, 256>>>(hf, agg);
    gemm_tc_kernel<256, true, true><<<ggrid, 256>>>(agg, WH + offW2,
                                                    b2, g2, be2, m2, v2, hf);

    // ---- layer 3: gather h_fp16 (C=256, no weight), GEMM + bias -> fp32 out -
    gather_kernel<256, false><<<(N_NODES + 7) / 8, 256>>>(hf, agg);
    gemm_tc_kernel<256, false, false><<<ggrid, 256>>>(agg, WH + offW3,
                                                      b3, nullptr, nullptr,
                                                      nullptr, nullptr, d_out);
}

// round 13
// speedup vs baseline: 2.4923x; 1.0633x over previous
#include <cuda_runtime.h>
#include <cuda_fp16.h>

#define N_NODES 50000
#define N_EDGES 1600000
#define C_OUT   256
#define SCAN_BLOCKS 196   // ceil(50000/256)
#define W1_N (256*128)
#define W2_N (256*256)
#define W_TOTAL (W1_N + 2*W2_N)

// prep_kernel block ranges
#define SPLIT_BLOCKS 640                   // ceil(W_TOTAL/256)
#define X2H_BLOCKS   6250                  // N_NODES*128/4/256
#define HIST_BLOCKS  782                   // ceil(N_EDGES/8/256)
#define PREP_BLOCKS  (SPLIT_BLOCKS + X2H_BLOCKS + HIST_BLOCKS)

// ---------------- scratch (static device globals; allocation-free) ----------
__device__ int    g_is64;
__device__ int2   g_edge[N_EDGES];     // (src, __float_as_int(ew)) CSR-sorted
__device__ int    g_deg[N_NODES];
__device__ unsigned long long g_state[SCAN_BLOCKS];  // lookback scan state
__device__ int    g_rowoff[N_NODES + 1];
__device__ int    g_cursor[N_NODES];
__device__ __half g_xh[(size_t)N_NODES * 128];       // fp16 copy of input x
__device__ __half g_hf[(size_t)N_NODES * C_OUT];     // fp16 hidden activations
__device__ __half g_agg[(size_t)N_NODES * C_OUT];    // fp16 aggregate
__device__ __half g_WH[W_TOTAL];

__device__ __forceinline__ unsigned h2_as_u32(half2 v) {
    unsigned u;
    memcpy(&u, &v, 4);
    return u;
}

// d(16x8 f32) += A(16x16 f16) * B(16x8 f16)
__device__ __forceinline__ void mma_f16(float c[4], const unsigned a[4],
                                        const unsigned b[2]) {
    asm("mma.sync.aligned.m16n8k16.row.col.f32.f16.f16.f32 "
        "{%0,%1,%2,%3}, {%4,%5,%6,%7}, {%8,%9}, {%0,%1,%2,%3};"
        : "+f"(c[0]), "+f"(c[1]), "+f"(c[2]), "+f"(c[3])
        : "r"(a[0]), "r"(a[1]), "r"(a[2]), "r"(a[3]), "r"(b[0]), "r"(b[1]));
}

// 16-byte async copy gmem->smem; full=false zero-fills (src not read)
__device__ __forceinline__ void cp16(unsigned dst_smem, const void* src, bool full) {
    int sz = full ? 16 : 0;
    asm volatile("cp.async.cg.shared.global [%0], [%1], 16, %2;"
                 :: "r"(dst_smem), "l"(src), "r"(sz));
}
#define CP_COMMIT()  asm volatile("cp.async.commit_group;")
#define CP_WAIT(N)   asm volatile("cp.async.wait_group %0;" :: "n"(N))

// ---------------- fused prep: weight split + detect | x2h | degree hist -----
__global__ void prep_kernel(const float* __restrict__ W1,
                            const float* __restrict__ W2,
                            const float* __restrict__ W3,
                            const float* __restrict__ x,
                            const int* __restrict__ ei) {
    int blk = blockIdx.x;
    int tid = threadIdx.x;

    if (blk < SPLIT_BLOCKS) {
        // ---- weight split (block 0 also publishes g_is64 for fill) ----
        if (blk == 0) {
            __shared__ int nz;
            if (tid == 0) nz = 0;
            __syncthreads();
            if (tid < 64 && ei[2 * tid + 1] != 0) nz = 1;
            __syncthreads();
            if (tid == 0) g_is64 = (nz == 0) ? 1 : 0;
        }
        int i = blk * 256 + tid;
        if (i < W_TOTAL) {
            float v;
            if (i < W1_N)             v = W1[i];
            else if (i < W1_N + W2_N) v = W2[i - W1_N];
            else                      v = W3[i - W1_N - W2_N];
            g_WH[i] = __float2half_rn(v);
        }
    } else if (blk < SPLIT_BLOCKS + X2H_BLOCKS) {
        // ---- x -> fp16 ----
        int i = (blk - SPLIT_BLOCKS) * 256 + tid;   // < 1,600,000 exactly
        float4 v = ((const float4*)x)[i];
        half2 a = __halves2half2(__float2half_rn(v.x), __float2half_rn(v.y));
        half2 b = __halves2half2(__float2half_rn(v.z), __float2half_rn(v.w));
        ((uint2*)g_xh)[i] = make_uint2(h2_as_u32(a), h2_as_u32(b));
    } else {
        // ---- degree histogram (local is64 — can't rely on block 0 in-kernel) ----
        __shared__ int is64;
        if (tid == 0) is64 = 1;
        __syncthreads();
        if (tid < 64 && ei[2 * tid + 1] != 0) is64 = 0;
        __syncthreads();
        int e0 = ((blk - SPLIT_BLOCKS - X2H_BLOCKS) * 256 + tid) * 8;
        if (e0 >= N_EDGES) return;
        if (is64) {
            const int4* dw = (const int4*)(ei + 2 * (size_t)N_EDGES);
#pragma unroll
            for (int u = 0; u < 4; u++) {
                int4 v = dw[e0 / 2 + u];
                atomicAdd(&g_deg[v.x], 1);
                atomicAdd(&g_deg[v.z], 1);
            }
        } else {
            const int4* dw = (const int4*)(ei + N_EDGES);
#pragma unroll
            for (int u = 0; u < 2; u++) {
                int4 v = dw[e0 / 4 + u];
                atomicAdd(&g_deg[v.x], 1);
                atomicAdd(&g_deg[v.y], 1);
                atomicAdd(&g_deg[v.z], 1);
                atomicAdd(&g_deg[v.w], 1);
            }
        }
    }
}

// ---------------- single-kernel decoupled-lookback exclusive scan -----------
// state word: bits[63:62] = 2 (aggregate ready) | 3 (prefix ready); low 32 = value
__global__ void scan_kernel() {
    const unsigned long long FLAG_A = 2ULL << 62;
    const unsigned long long FLAG_P = 3ULL << 62;
    const unsigned long long VMASK  = 0xFFFFFFFFULL;
    int b = blockIdx.x;
    int tid = threadIdx.x;
    int i = b * 256 + tid;
    int v = (i < N_NODES) ? g_deg[i] : 0;

    // block-wide inclusive scan
    int lane = tid & 31, wid = tid >> 5;
    int x = v;
#pragma unroll
    for (int o = 1; o < 32; o <<= 1) {
        int t = __shfl_up_sync(~0u, x, o);
        if (lane >= o) x += t;
    }
    __shared__ int ws[8];
    if (lane == 31) ws[wid] = x;
    __syncthreads();
    if (wid == 0 && lane < 8) {
        int w = ws[lane];
#pragma unroll
        for (int o = 1; o < 8; o <<= 1) {
            int t = __shfl_up_sync(0xffu, w, o);
            if (lane >= o) w += t;
        }
        ws[lane] = w;
    }
    __syncthreads();
    int incl = x + (wid > 0 ? ws[wid - 1] : 0);
    int total = ws[7];

    // lookback (tid 0)
    __shared__ int prefix_sh;
    if (tid == 0) {
        if (b == 0) {
            prefix_sh = 0;
            atomicExch(&g_state[0], FLAG_P | (unsigned long long)total);
            g_rowoff[N_NODES] = N_EDGES;
        } else {
            atomicExch(&g_state[b], FLAG_A | (unsigned long long)total);
            long long run = 0;
            int j = b - 1;
            while (true) {
                unsigned long long s;
                do {
                    s = *(volatile unsigned long long*)(g_state + j);
                } while ((s >> 62) < 2);
                run += (long long)(s & VMASK);
                if ((s >> 62) == 3) break;   // hit a prefix
                j--;
            }
            atomicExch(&g_state[b],
                       FLAG_P | (unsigned long long)(run + total));
            prefix_sh = (int)run;
        }
    }
    __syncthreads();
    int excl = prefix_sh + incl - v;
    if (i < N_NODES) {
        g_rowoff[i] = excl;
        g_cursor[i] = excl;
    }
}

// decode 2 edges/thread, ew = mean(edge_attr,-1), scatter packed into CSR
__global__ void fill_kernel(const int* __restrict__ ei,
                            const float* __restrict__ ea) {
    int e0 = (blockIdx.x * blockDim.x + threadIdx.x) * 2;
    if (e0 >= N_EDGES) return;
    int s0, s1, d0, d1;
    if (g_is64) {
        int4 sv = *(const int4*)(ei + 2 * (size_t)e0);
        int4 dv = *(const int4*)(ei + 2 * (size_t)N_EDGES + 2 * (size_t)e0);
        s0 = sv.x; s1 = sv.z;
        d0 = dv.x; d1 = dv.z;
    } else {
        int2 sv = *(const int2*)(ei + e0);
        int2 dv = *(const int2*)(ei + N_EDGES + e0);
        s0 = sv.x; s1 = sv.y;
        d0 = dv.x; d1 = dv.y;
    }
    const float4* a4 = (const float4*)(ea + (size_t)e0 * 8);
    float4 u0 = a4[0], v0 = a4[1], u1 = a4[2], v1 = a4[3];
    float ew0 = (u0.x + u0.y + u0.z + u0.w + v0.x + v0.y + v0.z + v0.w) * 0.125f;
    float ew1 = (u1.x + u1.y + u1.z + u1.w + v1.x + v1.y + v1.z + v1.w) * 0.125f;
    int p0 = atomicAdd(&g_cursor[d0], 1);
    g_edge[p0] = make_int2(s0, __float_as_int(ew0));
    int p1 = atomicAdd(&g_cursor[d1], 1);
    g_edge[p1] = make_int2(s1, __float_as_int(ew1));
}

// ---------------- gather-aggregate (fp16 rows -> fp16 aggregate) ------------
template <int C, bool USE_W>
__global__ void gather_kernel(const __half* __restrict__ in,
                              __half* __restrict__ out) {
    constexpr int L = C / 8;        // lanes per node (16 or 32)
    constexpr int G = 256 / L;      // nodes per 256-thread block
    int grp  = threadIdx.x / L;
    int lane = threadIdx.x % L;
    int node = blockIdx.x * G + grp;
    if (node >= N_NODES) return;

    int e0 = g_rowoff[node];
    int e1 = g_rowoff[node + 1];
    const uint4* in4 = (const uint4*)in;   // row stride = C/8 uint4
    float acc[8];
#pragma unroll
    for (int q = 0; q < 8; q++) acc[q] = 0.f;

    int e = e0;
    for (; e + 8 <= e1; e += 8) {
        int2 p[8];
#pragma unroll
        for (int u = 0; u < 8; u++) p[u] = g_edge[e + u];
        uint4 r[8];
#pragma unroll
        for (int u = 0; u < 8; u++) r[u] = in4[(size_t)p[u].x * L + lane];
#pragma unroll
        for (int u = 0; u < 8; u++) {
            float w = USE_W ? __int_as_float(p[u].y) : 1.0f;
            half2 h0 = *(half2*)&r[u].x, h1 = *(half2*)&r[u].y;
            half2 h2 = *(half2*)&r[u].z, h3 = *(half2*)&r[u].w;
            float2 f0 = __half22float2(h0), f1 = __half22float2(h1);
            float2 f2 = __half22float2(h2), f3 = __half22float2(h3);
            acc[0] = fmaf(f0.x, w, acc[0]); acc[1] = fmaf(f0.y, w, acc[1]);
            acc[2] = fmaf(f1.x, w, acc[2]); acc[3] = fmaf(f1.y, w, acc[3]);
            acc[4] = fmaf(f2.x, w, acc[4]); acc[5] = fmaf(f2.y, w, acc[5]);
            acc[6] = fmaf(f3.x, w, acc[6]); acc[7] = fmaf(f3.y, w, acc[7]);
        }
    }
    for (; e < e1; e++) {
        int2 p = g_edge[e];
        float w = USE_W ? __int_as_float(p.y) : 1.0f;
        uint4 r = in4[(size_t)p.x * L + lane];
        half2 h0 = *(half2*)&r.x, h1 = *(half2*)&r.y;
        half2 h2 = *(half2*)&r.z, h3 = *(half2*)&r.w;
        float2 f0 = __half22float2(h0), f1 = __half22float2(h1);
        float2 f2 = __half22float2(h2), f3 = __half22float2(h3);
        acc[0] = fmaf(f0.x, w, acc[0]); acc[1] = fmaf(f0.y, w, acc[1]);
        acc[2] = fmaf(f1.x, w, acc[2]); acc[3] = fmaf(f1.y, w, acc[3]);
        acc[4] = fmaf(f2.x, w, acc[4]); acc[5] = fmaf(f2.y, w, acc[5]);
        acc[6] = fmaf(f3.x, w, acc[6]); acc[7] = fmaf(f3.y, w, acc[7]);
    }

    half2 hh[4];
#pragma unroll
    for (int q = 0; q < 4; q++)
        hh[q] = __halves2half2(__float2half_rn(acc[2 * q]),
                               __float2half_rn(acc[2 * q + 1]));
    uint4 pH = make_uint4(h2_as_u32(hh[0]), h2_as_u32(hh[1]),
                          h2_as_u32(hh[2]), h2_as_u32(hh[3]));
    *(uint4*)(out + (size_t)node * C + lane * 8) = pH;
}

// ---------------- tensor-core GEMM (fp16, cp.async double-buffered) ---------
// out[M,256] = A @ W^T + epilogue.  BM=128, BN=64, BK=32, 256 threads =
// 8 warps (4m x 2n), warp tile 32x32 = 2 m-atoms x 4 n-atoms, m16n8k16.
template <int K, bool BN_RELU, bool OUT_HALF>
__global__ void gemm_tc_kernel(const __half* __restrict__ A,
                               const __half* __restrict__ B,
                               const float* __restrict__ bias,
                               const float* __restrict__ gam,
                               const float* __restrict__ bet,
                               const float* __restrict__ mu,
                               const float* __restrict__ var,
                               void* __restrict__ out_v) {
    constexpr int BM = 128, BN = 64, BK = 32;
    constexpr int PK = 20;  // row pitch in half2: conflict-free frag LDS
    constexpr int NT = K / BK;
    __shared__ __align__(16) half2 sA[2][BM][PK];
    __shared__ __align__(16) half2 sB[2][BN][PK];

    int m0 = blockIdx.x * BM;
    int n0 = blockIdx.y * BN;
    int tid = threadIdx.x;
    int lane = tid & 31;
    int g = lane >> 2;        // 0..7
    int t = lane & 3;         // 0..3
    int wid = tid >> 5;       // 0..7
    int wm = wid & 3;         // warp m index (0..3)
    int wn = wid >> 2;        // warp n index (0..1)

    int arow = tid >> 1;            // 0..127
    int akq  = (tid & 1) * 16;      // 0 or 16 (halves)
    int brow = tid >> 2;            // 0..63
    int bkq  = (tid & 3) * 8;       // 0,8,16,24 (halves)

    int arow_g   = m0 + arow;
    bool a_ok    = arow_g < N_NODES;
    int arow_cl  = a_ok ? arow_g : 0;       // clamped for address calc

    float acc[2][4][4];
#pragma unroll
    for (int i = 0; i < 2; i++)
#pragma unroll
        for (int j = 0; j < 4; j++)
#pragma unroll
            for (int c = 0; c < 4; c++) acc[i][j][c] = 0.f;

    // async-load tile kt into buffer bf
    auto load_tile = [&](int kt, int bf) {
        const __half* ap = A + (size_t)arow_cl * K + kt * BK + akq;
        unsigned dA0 = (unsigned)__cvta_generic_to_shared(&sA[bf][arow][akq / 2]);
        cp16(dA0, ap, a_ok);
        cp16(dA0 + 16, ap + 8, a_ok);
        const __half* bp = B + (size_t)(n0 + brow) * K + kt * BK + bkq;
        unsigned dB = (unsigned)__cvta_generic_to_shared(&sB[bf][brow][bkq / 2]);
        cp16(dB, bp, true);
    };

    load_tile(0, 0);
    CP_COMMIT();

#pragma unroll 1
    for (int it = 0; it < NT; it++) {
        int buf = it & 1;
        if (it + 1 < NT) {
            load_tile(it + 1, buf ^ 1);
            CP_COMMIT();
            CP_WAIT(1);
        } else {
            CP_WAIT(0);
        }
        __syncthreads();

#pragma unroll
        for (int ko = 0; ko < 2; ko++) {   // two k16 steps per BK=32 tile
            int kb = ko * 8;               // half2 offset
            unsigned ah[2][4], bh[4][2];
#pragma unroll
            for (int i = 0; i < 2; i++) {
                int rm = wm * 32 + i * 16;
                ah[i][0] = h2_as_u32(sA[buf][rm + g][kb + t]);
                ah[i][1] = h2_as_u32(sA[buf][rm + g + 8][kb + t]);
                ah[i][2] = h2_as_u32(sA[buf][rm + g][kb + t + 4]);
                ah[i][3] = h2_as_u32(sA[buf][rm + g + 8][kb + t + 4]);
            }
#pragma unroll
            for (int j = 0; j < 4; j++) {
                int cn = wn * 32 + j * 8;
                bh[j][0] = h2_as_u32(sB[buf][cn + g][kb + t]);
                bh[j][1] = h2_as_u32(sB[buf][cn + g][kb + t + 4]);
            }
#pragma unroll
            for (int i = 0; i < 2; i++)
#pragma unroll
                for (int j = 0; j < 4; j++)
                    mma_f16(acc[i][j], ah[i], bh[j]);
        }
        __syncthreads();   // all warps done with buf before it is reloaded
    }

    // ---- epilogue: +bias, optional BN(eval)+ReLU ----
#pragma unroll
    for (int j = 0; j < 4; j++) {
        int n = n0 + wn * 32 + j * 8 + 2 * t;
        float b0 = bias[n], b1 = bias[n + 1];
        float s0 = 0.f, s1 = 0.f, t0 = 0.f, t1 = 0.f;
        if (BN_RELU) {
            s0 = gam[n] * rsqrtf(var[n] + 1e-5f);
            t0 = bet[n] - mu[n] * s0;
            s1 = gam[n + 1] * rsqrtf(var[n + 1] + 1e-5f);
            t1 = bet[n + 1] - mu[n + 1] * s1;
        }
#pragma unroll
        for (int i = 0; i < 2; i++) {
            int r0 = m0 + wm * 32 + i * 16 + g;
            int r1 = r0 + 8;
            float z0 = acc[i][j][0] + b0;
            float z1 = acc[i][j][1] + b1;
            float z2 = acc[i][j][2] + b0;
            float z3 = acc[i][j][3] + b1;
            if (BN_RELU) {
                z0 = fmaxf(fmaf(z0, s0, t0), 0.f);
                z1 = fmaxf(fmaf(z1, s1, t1), 0.f);
                z2 = fmaxf(fmaf(z2, s0, t0), 0.f);
                z3 = fmaxf(fmaf(z3, s1, t1), 0.f);
            }
            if (OUT_HALF) {
                __half* oh = (__half*)out_v;
                half2 p0 = __halves2half2(__float2half_rn(z0), __float2half_rn(z1));
                half2 p1 = __halves2half2(__float2half_rn(z2), __float2half_rn(z3));
                if (r0 < N_NODES)
                    *(half2*)(oh + (size_t)r0 * C_OUT + n) = p0;
                if (r1 < N_NODES)
                    *(half2*)(oh + (size_t)r1 * C_OUT + n) = p1;
            } else {
                float* of = (float*)out_v;
                if (r0 < N_NODES)
                    *(float2*)(of + (size_t)r0 * C_OUT + n) = make_float2(z0, z1);
                if (r1 < N_NODES)
                    *(float2*)(of + (size_t)r1 * C_OUT + n) = make_float2(z2, z3);
            }
        }
    }
}

// ---------------- launch ----------------------------------------------------
extern "C" void kernel_launch(void* const* d_in, const int* in_sizes, int n_in,
                              void* d_out, int out_size) {
    const float* x   = (const float*)d_in[0];
    const int*   ei  = (const int*)d_in[1];
    const float* ea  = (const float*)d_in[2];
    const float* W1  = (const float*)d_in[3];
    const float* b1  = (const float*)d_in[4];
    const float* g1  = (const float*)d_in[5];
    const float* be1 = (const float*)d_in[6];
    const float* m1  = (const float*)d_in[7];
    const float* v1  = (const float*)d_in[8];
    const float* W2  = (const float*)d_in[9];
    const float* b2  = (const float*)d_in[10];
    const float* g2  = (const float*)d_in[11];
    const float* be2 = (const float*)d_in[12];
    const float* m2  = (const float*)d_in[13];
    const float* v2  = (const float*)d_in[14];
    const float* W3  = (const float*)d_in[15];
    const float* b3  = (const float*)d_in[16];

    void *p_agg, *p_hf, *p_xh, *p_deg, *p_state, *p_WH;
    cudaGetSymbolAddress(&p_agg, g_agg);
    cudaGetSymbolAddress(&p_hf, g_hf);
    cudaGetSymbolAddress(&p_xh, g_xh);
    cudaGetSymbolAddress(&p_deg, g_deg);
    cudaGetSymbolAddress(&p_state, g_state);
    cudaGetSymbolAddress(&p_WH, g_WH);
    __half* agg = (__half*)p_agg;
    __half* hf  = (__half*)p_hf;
    __half* xh  = (__half*)p_xh;
    __half* WH  = (__half*)p_WH;
    const int offW2 = W1_N;
    const int offW3 = W1_N + W2_N;

    // ---- CSR build + conversions (once) ----
    cudaMemsetAsync(p_deg, 0, N_NODES * sizeof(int));
    cudaMemsetAsync(p_state, 0, SCAN_BLOCKS * sizeof(unsigned long long));
    prep_kernel<<<PREP_BLOCKS, 256>>>(W1, W2, W3, x, ei);
    scan_kernel<<<SCAN_BLOCKS, 256>>>();
    fill_kernel<<<(N_EDGES / 2 + 255) / 256, 256>>>(ei, ea);

    dim3 ggrid((N_NODES + 127) / 128, 4);  // 391 x 4, BM=128 BN=64

    // ---- layer 1: gather x_fp16 (C=128), GEMM K=128 + BN1 + ReLU -> fp16 h --
    gather_kernel<128, true><<<(N_NODES + 15) / 16, 256>>>(xh, agg);
    gemm_tc_kernel<128, true, true><<<ggrid, 256>>>(agg, WH,
                                                    b1, g1, be1, m1, v1, hf);

    // ---- layer 2: gather h_fp16 (C=256), GEMM K=256 + BN2 + ReLU -> fp16 h --
    gather_kernel<256, true><<<(N_NODES + 7) / 8, 256>>>(hf, agg);
    gemm_tc_kernel<256, true, true><<<ggrid, 256>>>(agg, WH + offW2,
                                                    b2, g2, be2, m2, v2, hf);

    // ---- layer 3: gather h_fp16 (C=256, no weight), GEMM + bias -> fp32 out -
    gather_kernel<256, false><<<(N_NODES + 7) / 8, 256>>>(hf, agg);
    gemm_tc_kernel<256, false, false><<<ggrid, 256>>>(agg, WH + offW3,
                                                      b3, nullptr, nullptr,
                                                      nullptr, nullptr, d_out);
}